// round 11
// baseline (speedup 1.0000x reference)
#include <cuda_runtime.h>
#include <cuda_fp16.h>
#include <math.h>
#include <stdint.h>

#define Bq 2
#define Lq 4096
#define Dq 1024
#define Hq 16
#define HDq 64
#define NCH 32
#define CH 128
#define BHL (Bq*Hq*Lq)

// ---- fp16 cp.async GEMM geometry: 128M x 256N x 32K, 4 stages ----
#define HSTG 4
#define HBK 32
#define HASTR 40
#define ASTG (128*HASTR)            // halves per A stage
#define BSTG (256*HASTR)            // halves per B stage
#define HSMEM ((HSTG*(ASTG+BSTG))*2)  // 122880 bytes

// ---------------- device scratch (no allocations allowed) ----------------
__device__ __half g_xh[Bq*Lq*Dq];         // half x [8192][1024]
__device__ __half g_wh[4*Dq*Dq];          // W^T [n][k] for Wq,Wk,Wv,Wo
__device__ __half g_gwh[256*Dq];          // packed gate weights^T (padded to 256 n)
__device__ __half g_omixh[Bq*Lq*Dq];
__device__ float g_q[Bq*Hq*Lq*HDq];
__device__ float g_k[Bq*Hq*Lq*HDq];       // silu only (no beta)
__device__ float g_v[Bq*Hq*Lq*HDq];       // silu only (no beta)
__device__ float g_beta[BHL];
__device__ float g_fd[BHL];
__device__ float g_sd[BHL];
__device__ float g_fg[BHL];
__device__ float g_sg[BHL];
__device__ float g_psi[BHL];
__device__ float g_gf[Bq*Hq*NCH];
__device__ float g_gs[Bq*Hq*NCH];
__device__ float g_Af[Bq*Hq*NCH*HDq*HDq];
__device__ float g_As[Bq*Hq*NCH*HDq*HDq];

__device__ __forceinline__ float sigm(float x) { return 1.f / (1.f + expf(-x)); }

__device__ __forceinline__ uint32_t smem_u32(const void* p) {
    return (uint32_t)__cvta_generic_to_shared(p);
}

__device__ __forceinline__ void cp16h(__half* dst, const __half* src) {
    uint32_t d = (uint32_t)__cvta_generic_to_shared(dst);
    asm volatile("cp.async.ca.shared.global [%0], [%1], 16;" :: "r"(d), "l"(src));
}

__device__ __forceinline__ void ldsm_x4(
    uint32_t& r0, uint32_t& r1, uint32_t& r2, uint32_t& r3, uint32_t addr)
{
    asm volatile("ldmatrix.sync.aligned.m8n8.x4.shared.b16 {%0,%1,%2,%3}, [%4];"
        : "=r"(r0), "=r"(r1), "=r"(r2), "=r"(r3) : "r"(addr));
}

// fp16 k16 mma, f32 accum
__device__ __forceinline__ void mma_f16(
    float& c0, float& c1, float& c2, float& c3,
    uint32_t a0, uint32_t a1, uint32_t a2, uint32_t a3,
    uint32_t b0, uint32_t b1)
{
    asm volatile(
        "mma.sync.aligned.m16n8k16.row.col.f32.f16.f16.f32 "
        "{%0,%1,%2,%3}, {%4,%5,%6,%7}, {%8,%9}, {%0,%1,%2,%3};"
        : "+f"(c0), "+f"(c1), "+f"(c2), "+f"(c3)
        : "r"(a0), "r"(a1), "r"(a2), "r"(a3), "r"(b0), "r"(b1));
}

// ---------------- K0a: x -> half ----------------
__global__ __launch_bounds__(256) void xhalf_kernel(const float* __restrict__ x)
{
    size_t i = (size_t)blockIdx.x * 256 + threadIdx.x;
    const float4* s = (const float4*)x;
    float4 v0 = s[i * 2], v1 = s[i * 2 + 1];
    __half2 h0 = __floats2half2_rn(v0.x, v0.y);
    __half2 h1 = __floats2half2_rn(v0.z, v0.w);
    __half2 h2 = __floats2half2_rn(v1.x, v1.y);
    __half2 h3 = __floats2half2_rn(v1.z, v1.w);
    uint4 o;
    o.x = *(uint32_t*)&h0; o.y = *(uint32_t*)&h1;
    o.z = *(uint32_t*)&h2; o.w = *(uint32_t*)&h3;
    ((uint4*)g_xh)[i] = o;
}

// ---------------- K0b: W -> half, transposed to [n][k] ----------------
__global__ void wtrans_kernel(
    const float* __restrict__ Wq, const float* __restrict__ Wk,
    const float* __restrict__ Wv, const float* __restrict__ Wo)
{
    __shared__ __half tile[32][33];
    const int z = blockIdx.z;
    const float* W = (z == 0) ? Wq : (z == 1) ? Wk : (z == 2) ? Wv : Wo;
    __half* WT = g_wh + (size_t)z * Dq * Dq;
    const int x0 = blockIdx.x * 32;
    const int y0 = blockIdx.y * 32;
    const int tx = threadIdx.x, ty = threadIdx.y;
#pragma unroll
    for (int i = 0; i < 4; i++)
        tile[ty + 8 * i][tx] = __float2half_rn(W[(size_t)(y0 + ty + 8 * i) * 1024 + x0 + tx]);
    __syncthreads();
#pragma unroll
    for (int i = 0; i < 4; i++)
        WT[(size_t)(x0 + ty + 8 * i) * 1024 + y0 + tx] = tile[tx][ty + 8 * i];
}

// ---------------- K0c: pack 5 gate weights -> [256 n][1024 k] half ---------
__global__ __launch_bounds__(256) void gwpack_kernel(
    const float* __restrict__ Wbm, const float* __restrict__ Wfd,
    const float* __restrict__ Wsd, const float* __restrict__ Wfg,
    const float* __restrict__ Wsg)
{
    int idx = blockIdx.x * 256 + threadIdx.x;   // 0..262143
    int n = idx >> 10, k = idx & 1023;
    __half val = __float2half_rn(0.f);
    if (n < 80) {
        int which = n >> 4, h = n & 15;
        const float* Wp = (which == 0) ? Wbm : (which == 1) ? Wfd
                         : (which == 2) ? Wsd : (which == 3) ? Wfg : Wsg;
        val = __float2half_rn(Wp[k * 16 + h]);
    }
    g_gwh[n * 1024 + k] = val;
}

// ---------------- K1(+K2)/K7: fp16 GEMM, 128x256 tile, warp 64x64 -----------
// phase 0: 832 blocks — [0,768) QKV (silu+head), [768,832) gates (N=256 pad).
// phase 1: 256 blocks — K7 plain fp32 C0.
__global__ __launch_bounds__(256, 1) void gemm_f16_kernel(
    const __half* __restrict__ A, const __half* __restrict__ WTq,
    const __half* __restrict__ WTg,
    float* __restrict__ C0, float* __restrict__ C1, float* __restrict__ C2,
    const float* __restrict__ fdb, const float* __restrict__ sdb,
    int phase)
{
    extern __shared__ __half smh[];
    __half* As = smh;                          // [HSTG][128][HASTR]
    __half* Bs = smh + HSTG * ASTG;            // [HSTG][256][HASTR]

    const int bid = blockIdx.x;
    int mode, bm, bn, z = 0;
    const __half* WT;
    float* C = C0;
    if (phase == 0) {
        if (bid < 768) {
            z = bid >> 8;
            int idx = bid & 255;
            bn = (idx & 3) * 256;
            bm = (idx >> 2) * 128;
            mode = 1;
            WT = WTq + (size_t)z * Dq * Dq;
            C = (z == 0) ? C0 : (z == 1) ? C1 : C2;
        } else {
            bm = (bid - 768) * 128;
            bn = 0;
            mode = 3;
            WT = WTg;
        }
    } else {
        bn = (bid & 3) * 256;
        bm = (bid >> 2) * 128;
        mode = 0;
        WT = WTq;
    }

    const int tid = threadIdx.x;
    const int lane = tid & 31;
    const int wid = tid >> 5;
    const int gid = lane >> 2;
    const int tig = lane & 3;
    const int warpM = (wid & 1) * 64;
    const int warpN = (wid >> 1) * 64;

    const int l_r = tid >> 2;            // 0..63
    const int l_c = (tid & 3) * 8;       // 0,8,16,24

    // ldmatrix per-lane offsets (halves)
    const int a_lrow = lane & 15;
    const int a_lcol = (lane >> 4) * 8;
    const int b_lrow = ((lane >> 4) & 1) * 8 + (lane & 7);
    const int b_lcol = ((lane >> 3) & 1) * 8;

    float acc[4][8][4];
#pragma unroll
    for (int mt = 0; mt < 4; mt++)
#pragma unroll
        for (int nt = 0; nt < 8; nt++)
#pragma unroll
            for (int c = 0; c < 4; c++) acc[mt][nt][c] = 0.f;

    const __half* Ab0 = A + (size_t)(bm + l_r) * 1024 + l_c;
    const __half* Ab1 = A + (size_t)(bm + l_r + 64) * 1024 + l_c;
    const __half* Bb0 = WT + (size_t)(bn + l_r) * 1024 + l_c;
    const __half* Bb1 = WT + (size_t)(bn + l_r + 64) * 1024 + l_c;
    const __half* Bb2 = WT + (size_t)(bn + l_r + 128) * 1024 + l_c;
    const __half* Bb3 = WT + (size_t)(bn + l_r + 192) * 1024 + l_c;
    __half* AsD0 = As + l_r * HASTR + l_c;
    __half* AsD1 = As + (l_r + 64) * HASTR + l_c;
    __half* BsD0 = Bs + l_r * HASTR + l_c;
    __half* BsD1 = Bs + (l_r + 64) * HASTR + l_c;
    __half* BsD2 = Bs + (l_r + 128) * HASTR + l_c;
    __half* BsD3 = Bs + (l_r + 192) * HASTR + l_c;

    const uint32_t AsU = smem_u32(As);
    const uint32_t BsU = smem_u32(Bs);

#pragma unroll
    for (int s = 0; s < HSTG - 1; s++) {
        int k0 = s * HBK;
        cp16h(AsD0 + s * ASTG, Ab0 + k0);
        cp16h(AsD1 + s * ASTG, Ab1 + k0);
        cp16h(BsD0 + s * BSTG, Bb0 + k0);
        cp16h(BsD1 + s * BSTG, Bb1 + k0);
        cp16h(BsD2 + s * BSTG, Bb2 + k0);
        cp16h(BsD3 + s * BSTG, Bb3 + k0);
        asm volatile("cp.async.commit_group;");
    }

#pragma unroll 1
    for (int t = 0; t < 32; t++) {
        asm volatile("cp.async.wait_group 2;");
        __syncthreads();

        if (t + 3 < 32) {
            int s = (t + 3) & 3;
            int k0 = (t + 3) * HBK;
            cp16h(AsD0 + s * ASTG, Ab0 + k0);
            cp16h(AsD1 + s * ASTG, Ab1 + k0);
            cp16h(BsD0 + s * BSTG, Bb0 + k0);
            cp16h(BsD1 + s * BSTG, Bb1 + k0);
            cp16h(BsD2 + s * BSTG, Bb2 + k0);
            cp16h(BsD3 + s * BSTG, Bb3 + k0);
        }
        asm volatile("cp.async.commit_group;");

        const uint32_t AscU = AsU + (uint32_t)((t & 3) * ASTG) * 2u;
        const uint32_t BscU = BsU + (uint32_t)((t & 3) * BSTG) * 2u;
#pragma unroll
        for (int ks = 0; ks < 2; ks++) {
            const int kb = ks * 16;
            uint32_t af[4][4];
#pragma unroll
            for (int mt = 0; mt < 4; mt++) {
                uint32_t addr = AscU +
                    (uint32_t)((warpM + mt * 16 + a_lrow) * HASTR + kb + a_lcol) * 2u;
                ldsm_x4(af[mt][0], af[mt][1], af[mt][2], af[mt][3], addr);
            }
            uint32_t br[4][4];
#pragma unroll
            for (int np = 0; np < 4; np++) {
                uint32_t addr = BscU +
                    (uint32_t)((warpN + np * 16 + b_lrow) * HASTR + kb + b_lcol) * 2u;
                ldsm_x4(br[np][0], br[np][1], br[np][2], br[np][3], addr);
            }
#pragma unroll
            for (int nt = 0; nt < 8; nt++) {
                uint32_t b0 = br[nt >> 1][(nt & 1) * 2 + 0];
                uint32_t b1 = br[nt >> 1][(nt & 1) * 2 + 1];
#pragma unroll
                for (int mt = 0; mt < 4; mt++) {
                    mma_f16(acc[mt][nt][0], acc[mt][nt][1], acc[mt][nt][2], acc[mt][nt][3],
                            af[mt][0], af[mt][1], af[mt][2], af[mt][3], b0, b1);
                }
            }
        }
    }

    // epilogue
#pragma unroll
    for (int mt = 0; mt < 4; mt++) {
#pragma unroll
        for (int nt = 0; nt < 8; nt++) {
            int row = bm + warpM + mt * 16 + gid;
            int col = bn + warpN + nt * 8 + tig * 2;
#pragma unroll
            for (int half_ = 0; half_ < 2; half_++) {
                int r = row + half_ * 8;
                float v0 = acc[mt][nt][half_ * 2 + 0];
                float v1 = acc[mt][nt][half_ * 2 + 1];
                int bb = r >> 12, l = r & 4095;
                if (mode == 1) {
                    v0 = v0 * (1.f / (1.f + expf(-v0)));
                    v1 = v1 * (1.f / (1.f + expf(-v1)));
                    int h = col >> 6, hd = col & 63;
                    *(float2*)(C + (((size_t)(bb * Hq + h) * Lq + l) * HDq) + hd) =
                        make_float2(v0, v1);
                } else if (mode == 3) {
#pragma unroll
                    for (int cc = 0; cc < 2; cc++) {
                        int cl = col + cc;
                        if (cl < 80) {
                            int which = cl >> 4, h = cl & 15;
                            float s = (cc == 0) ? v0 : v1;
                            if (which == 1) s += fdb[h];
                            if (which == 2) s += sdb[h];
                            float val = sigm(s);
                            float* dst = (which == 0) ? g_beta : (which == 1) ? g_fd
                                        : (which == 2) ? g_sd : (which == 3) ? g_fg : g_sg;
                            dst[(bb * Hq + h) * Lq + l] = val;
                        }
                    }
                } else {
                    *(float2*)(C + (size_t)r * 1024 + col) = make_float2(v0, v1);
                }
            }
        }
    }
}

// ---------------- K4: outer products + psi/surprise + chunk decay (fused) ---
__global__ __launch_bounds__(256) void outer_kernel()
{
    __shared__ float Ks[64 * 64];
    __shared__ float Vs[64 * 64];
    __shared__ float S2[64];
    __shared__ float fdm_s[128];
    __shared__ float sdm_s[128];
    const int bhn = blockIdx.x;
    const int bh = bhn / NCH, n = bhn % NCH;
    const int t = threadIdx.x;
    const int d0 = (t & 15) * 4;
    const int e0 = (t >> 4) * 4;
    const int posbase = bh * Lq + n * CH;

    float af[4][4], as_[4][4];
#pragma unroll
    for (int i = 0; i < 4; i++)
#pragma unroll
        for (int j = 0; j < 4; j++) { af[i][j] = 0.f; as_[i][j] = 0.f; }

    for (int half_ = 0; half_ < 2; half_++) {
        size_t base = ((size_t)(posbase + half_ * 64)) * HDq;
        for (int i = t; i < 1024; i += 256) {
            int row = i >> 4;
            float b = g_beta[posbase + half_ * 64 + row];
            float4 k4 = ((const float4*)(g_k + base))[i];
            float4 v4 = ((const float4*)(g_v + base))[i];
            k4.x *= b; k4.y *= b; k4.z *= b; k4.w *= b;
            v4.x *= b; v4.y *= b; v4.z *= b; v4.w *= b;
            ((float4*)Ks)[i] = k4;
            ((float4*)Vs)[i] = v4;
        }
        __syncthreads();

        {
            int r = t >> 2, q = t & 3;
            const float4* krow = (const float4*)&Ks[r * 64 + q * 16];
            const float4* vrow = (const float4*)&Vs[r * 64 + q * 16];
            float kk = 0.f, vv = 0.f, kv = 0.f;
#pragma unroll
            for (int j = 0; j < 4; j++) {
                float4 a = krow[j], b = vrow[j];
                kk += a.x * a.x + a.y * a.y + a.z * a.z + a.w * a.w;
                vv += b.x * b.x + b.y * b.y + b.z * b.z + b.w * b.w;
                kv += a.x * b.x + a.y * b.y + a.z * b.z + a.w * b.w;
            }
            kk += __shfl_xor_sync(0xffffffffu, kk, 1);
            kk += __shfl_xor_sync(0xffffffffu, kk, 2);
            vv += __shfl_xor_sync(0xffffffffu, vv, 1);
            vv += __shfl_xor_sync(0xffffffffu, vv, 2);
            kv += __shfl_xor_sync(0xffffffffu, kv, 1);
            kv += __shfl_xor_sync(0xffffffffu, kv, 2);
            if (q == 0) {
                float kn = sqrtf(kk) + 1e-8f;
                float vn = sqrtf(vv) + 1e-8f;
                float praw = fabsf(kv) / (kn * vn);
                float psi = sigm(3.f * praw);
                float sur = sigm((psi - 0.5f) * 10.f);
                S2[r] = sur * sur;
                int p = posbase + half_ * 64 + r;
                g_psi[p] = psi;
                fdm_s[half_ * 64 + r] = g_fd[p] * (1.f - 0.1f * psi);
                sdm_s[half_ * 64 + r] = g_sd[p] * (1.f - 0.05f * psi);
            }
        }
        __syncthreads();

#pragma unroll 4
        for (int l = 0; l < 64; l++) {
            float4 vv4 = *(float4*)&Vs[l * 64 + d0];
            float4 kk4 = *(float4*)&Ks[l * 64 + e0];
            float s2 = S2[l];
            float v[4] = {vv4.x, vv4.y, vv4.z, vv4.w};
            float k[4] = {kk4.x, kk4.y, kk4.z, kk4.w};
            float vs[4] = {v[0] * s2, v[1] * s2, v[2] * s2, v[3] * s2};
#pragma unroll
            for (int i = 0; i < 4; i++)
#pragma unroll
                for (int j = 0; j < 4; j++) {
                    af[i][j] += v[i] * k[j];
                    as_[i][j] += vs[i] * k[j];
                }
        }
        __syncthreads();
    }

    if (t < 32) {
        float f = 0.f, s = 0.f;
#pragma unroll
        for (int j = t; j < 128; j += 32) { f += fdm_s[j]; s += sdm_s[j]; }
#pragma unroll
        for (int off = 16; off; off >>= 1) {
            f += __shfl_xor_sync(0xffffffffu, f, off);
            s += __shfl_xor_sync(0xffffffffu, s, off);
        }
        if (t == 0) {
            float gf = f * (1.f / 128.f), gs = s * (1.f / 128.f);
#pragma unroll
            for (int i = 0; i < 7; i++) { gf *= gf; gs *= gs; }
            g_gf[bhn] = gf;
            g_gs[bhn] = gs;
        }
    }

    size_t abase = (size_t)bhn * 4096;
#pragma unroll
    for (int i = 0; i < 4; i++) {
        *(float4*)&g_Af[abase + (d0 + i) * 64 + e0] =
            make_float4(af[i][0], af[i][1], af[i][2], af[i][3]);
        *(float4*)&g_As[abase + (d0 + i) * 64 + e0] =
            make_float4(as_[i][0], as_[i][1], as_[i][2], as_[i][3]);
    }
}

// ---------------- K5: decayed prefix scan over chunks (in-place) ------------
__global__ void scan_kernel()
{
    int bh = blockIdx.x >> 4;
    int eb = blockIdx.x & 15;
    int entry = eb * 256 + threadIdx.x;
    float sfv = 0.f, ssv = 0.f;
#pragma unroll 1
    for (int n = 0; n < NCH; n++) {
        int bhn = bh * NCH + n;
        float gf = g_gf[bhn], gs = g_gs[bhn];
        size_t idx = (size_t)bhn * 4096 + entry;
        sfv = sfv * gf + g_Af[idx]; g_Af[idx] = sfv;
        ssv = ssv * gs + g_As[idx]; g_As[idx] = ssv;
    }
}

// ---------------- K6: O = Q @ S (fast+slow), gate/alpha mix -> omix (half) --
__global__ __launch_bounds__(256) void outmix_kernel()
{
    __shared__ float Sf[4096];
    __shared__ float Ss[4096];
    __shared__ float Qs[32 * 64];
    __shared__ float gA[32], gB[32];
    const int bhn = blockIdx.x;
    const int bh = bhn / NCH, n = bhn % NCH;
    const int b = bh >> 4, h = bh & 15;
    const int t = threadIdx.x;

    size_t abase = (size_t)bhn * 4096;
    for (int i = t; i < 1024; i += 256) {
        ((float4*)Sf)[i] = ((const float4*)(g_Af + abase))[i];
        ((float4*)Ss)[i] = ((const float4*)(g_As + abase))[i];
    }

    const int d = t & 63;
    const int lb = (t >> 6) * 8;

    for (int pass = 0; pass < 4; pass++) {
        int l0 = pass * 32;
        size_t qbase = ((size_t)bh * Lq + n * CH + l0) * HDq;
        for (int i = t; i < 512; i += 256)
            ((float4*)Qs)[i] = ((const float4*)(g_q + qbase))[i];
        if (t < 32) {
            int p = bh * Lq + n * CH + l0 + t;
            float psi = g_psi[p];
            float alpha = 0.5f + 0.3f * psi;
            gA[t] = alpha * g_fg[p];
            gB[t] = (1.f - alpha) * g_sg[p];
        }
        __syncthreads();

        float accf[8], accs[8];
#pragma unroll
        for (int l = 0; l < 8; l++) { accf[l] = 0.f; accs[l] = 0.f; }
#pragma unroll 8
        for (int e = 0; e < 64; e += 2) {
            float sf0 = Sf[e * 64 + d];
            float sf1 = Sf[(e + 1) * 64 + d];
            float ss0 = Ss[e * 64 + d];
            float ss1 = Ss[(e + 1) * 64 + d];
#pragma unroll
            for (int l = 0; l < 8; l++) {
                float2 q2 = *(float2*)&Qs[(lb + l) * 64 + e];
                accf[l] += q2.x * sf0 + q2.y * sf1;
                accs[l] += q2.x * ss0 + q2.y * ss1;
            }
        }
#pragma unroll
        for (int l = 0; l < 8; l++) {
            int ll = lb + l;
            float val = gA[ll] * accf[l] + gB[ll] * accs[l];
            int lglob = n * CH + l0 + ll;
            g_omixh[((size_t)b * Lq + lglob) * Dq + h * HDq + d] = __float2half_rn(val);
        }
        __syncthreads();
    }
}

// ---------------- launch ----------------
extern "C" void kernel_launch(void* const* d_in, const int* in_sizes, int n_in,
                              void* d_out, int out_size)
{
    const float* x   = (const float*)d_in[0];
    const float* Wq  = (const float*)d_in[1];
    const float* Wk  = (const float*)d_in[2];
    const float* Wv  = (const float*)d_in[3];
    const float* Wb  = (const float*)d_in[4];
    const float* Wfd = (const float*)d_in[5];
    const float* fdb = (const float*)d_in[6];
    const float* Wsd = (const float*)d_in[7];
    const float* sdb = (const float*)d_in[8];
    const float* Wfg = (const float*)d_in[9];
    const float* Wsg = (const float*)d_in[10];
    const float* Wo  = (const float*)d_in[11];
    float* out = (float*)d_out;

    void *p_q = nullptr, *p_k = nullptr, *p_v = nullptr;
    void *p_xh = nullptr, *p_wh = nullptr, *p_gwh = nullptr, *p_oh = nullptr;
    cudaGetSymbolAddress(&p_q, g_q);
    cudaGetSymbolAddress(&p_k, g_k);
    cudaGetSymbolAddress(&p_v, g_v);
    cudaGetSymbolAddress(&p_xh, g_xh);
    cudaGetSymbolAddress(&p_wh, g_wh);
    cudaGetSymbolAddress(&p_gwh, g_gwh);
    cudaGetSymbolAddress(&p_oh, g_omixh);

    cudaFuncSetAttribute(gemm_f16_kernel,
                         cudaFuncAttributeMaxDynamicSharedMemorySize, HSMEM);

    // K0: conversions & packing
    xhalf_kernel<<<4096, 256>>>(x);
    wtrans_kernel<<<dim3(32, 32, 4), dim3(32, 8)>>>(Wq, Wk, Wv, Wo);
    gwpack_kernel<<<1024, 256>>>(Wb, Wfd, Wsd, Wfg, Wsg);

    // K1+K2: fused QKV + gate projections (832 blocks)
    gemm_f16_kernel<<<832, 256, HSMEM>>>(
        (const __half*)p_xh, (const __half*)p_wh, (const __half*)p_gwh,
        (float*)p_q, (float*)p_k, (float*)p_v, fdb, sdb, 0);

    // K4: fused outer products + psi/surprise + chunk decay
    outer_kernel<<<Bq * Hq * NCH, 256>>>();

    // K5: decayed scan across chunks
    scan_kernel<<<Bq * Hq * 16, 256>>>();

    // K6: per-chunk output + gate mixing (half omix)
    outmix_kernel<<<Bq * Hq * NCH, 256>>>();

    // K7: output projection (256 blocks, plain epilogue)
    gemm_f16_kernel<<<256, 256, HSMEM>>>(
        (const __half*)p_oh, (const __half*)p_wh + (size_t)3 * Dq * Dq,
        (const __half*)p_gwh, out, out, out, fdb, sdb, 1);
}

// round 12
// speedup vs baseline: 1.3257x; 1.3257x over previous
#include <cuda_runtime.h>
#include <cuda_fp16.h>
#include <math.h>
#include <stdint.h>

#define Bq 2
#define Lq 4096
#define Dq 1024
#define Hq 16
#define HDq 64
#define NCH 32
#define CH 128
#define BHL (Bq*Hq*Lq)

// ---- fp16 cp.async GEMM geometry (round-10 proven config) ----
#define HSTG 4
#define HBK 32
#define HASTR 40
#define HSTAGE (128*HASTR)
#define HSMEM (HSTG*2*HSTAGE*2)

// ---------------- device scratch (no allocations allowed) ----------------
__device__ __half g_xh[Bq*Lq*Dq];         // half x [8192][1024]
__device__ __half g_wh[4*Dq*Dq];          // W^T [n][k] for Wq,Wk,Wv,Wo
__device__ __half g_gwh[128*Dq];          // packed gate weights^T
__device__ __half g_omixh[Bq*Lq*Dq];
__device__ __half g_q[Bq*Hq*Lq*HDq];      // half q (silu)
__device__ __half g_k[Bq*Hq*Lq*HDq];      // half k (silu, no beta)
__device__ __half g_v[Bq*Hq*Lq*HDq];      // half v (silu, no beta)
__device__ float g_beta[BHL];
__device__ float g_fd[BHL];
__device__ float g_sd[BHL];
__device__ float g_fg[BHL];
__device__ float g_sg[BHL];
__device__ float g_psi[BHL];
__device__ float g_gf[Bq*Hq*NCH];
__device__ float g_gs[Bq*Hq*NCH];
__device__ float g_Af[Bq*Hq*NCH*HDq*HDq];
__device__ float g_As[Bq*Hq*NCH*HDq*HDq];

__device__ __forceinline__ float sigm(float x) { return 1.f / (1.f + expf(-x)); }

__device__ __forceinline__ uint32_t smem_u32(const void* p) {
    return (uint32_t)__cvta_generic_to_shared(p);
}

__device__ __forceinline__ void cp16h(__half* dst, const __half* src) {
    uint32_t d = (uint32_t)__cvta_generic_to_shared(dst);
    asm volatile("cp.async.ca.shared.global [%0], [%1], 16;" :: "r"(d), "l"(src));
}

__device__ __forceinline__ void ldsm_x4(
    uint32_t& r0, uint32_t& r1, uint32_t& r2, uint32_t& r3, uint32_t addr)
{
    asm volatile("ldmatrix.sync.aligned.m8n8.x4.shared.b16 {%0,%1,%2,%3}, [%4];"
        : "=r"(r0), "=r"(r1), "=r"(r2), "=r"(r3) : "r"(addr));
}

// fp16 k16 mma, f32 accum
__device__ __forceinline__ void mma_f16(
    float& c0, float& c1, float& c2, float& c3,
    uint32_t a0, uint32_t a1, uint32_t a2, uint32_t a3,
    uint32_t b0, uint32_t b1)
{
    asm volatile(
        "mma.sync.aligned.m16n8k16.row.col.f32.f16.f16.f32 "
        "{%0,%1,%2,%3}, {%4,%5,%6,%7}, {%8,%9}, {%0,%1,%2,%3};"
        : "+f"(c0), "+f"(c1), "+f"(c2), "+f"(c3)
        : "r"(a0), "r"(a1), "r"(a2), "r"(a3), "r"(b0), "r"(b1));
}

// ---------------- K0a: x -> half ----------------
__global__ __launch_bounds__(256) void xhalf_kernel(const float* __restrict__ x)
{
    size_t i = (size_t)blockIdx.x * 256 + threadIdx.x;
    const float4* s = (const float4*)x;
    float4 v0 = s[i * 2], v1 = s[i * 2 + 1];
    __half2 h0 = __floats2half2_rn(v0.x, v0.y);
    __half2 h1 = __floats2half2_rn(v0.z, v0.w);
    __half2 h2 = __floats2half2_rn(v1.x, v1.y);
    __half2 h3 = __floats2half2_rn(v1.z, v1.w);
    uint4 o;
    o.x = *(uint32_t*)&h0; o.y = *(uint32_t*)&h1;
    o.z = *(uint32_t*)&h2; o.w = *(uint32_t*)&h3;
    ((uint4*)g_xh)[i] = o;
}

// ---------------- K0b: W -> half, transposed to [n][k] ----------------
__global__ void wtrans_kernel(
    const float* __restrict__ Wq, const float* __restrict__ Wk,
    const float* __restrict__ Wv, const float* __restrict__ Wo)
{
    __shared__ __half tile[32][33];
    const int z = blockIdx.z;
    const float* W = (z == 0) ? Wq : (z == 1) ? Wk : (z == 2) ? Wv : Wo;
    __half* WT = g_wh + (size_t)z * Dq * Dq;
    const int x0 = blockIdx.x * 32;
    const int y0 = blockIdx.y * 32;
    const int tx = threadIdx.x, ty = threadIdx.y;
#pragma unroll
    for (int i = 0; i < 4; i++)
        tile[ty + 8 * i][tx] = __float2half_rn(W[(size_t)(y0 + ty + 8 * i) * 1024 + x0 + tx]);
    __syncthreads();
#pragma unroll
    for (int i = 0; i < 4; i++)
        WT[(size_t)(x0 + ty + 8 * i) * 1024 + y0 + tx] = tile[tx][ty + 8 * i];
}

// ---------------- K0c: pack 5 gate weights -> [128 n][1024 k] half ---------
__global__ __launch_bounds__(256) void gwpack_kernel(
    const float* __restrict__ Wbm, const float* __restrict__ Wfd,
    const float* __restrict__ Wsd, const float* __restrict__ Wfg,
    const float* __restrict__ Wsg)
{
    int idx = blockIdx.x * 256 + threadIdx.x;
    int n = idx >> 10, k = idx & 1023;
    __half val = __float2half_rn(0.f);
    if (n < 80) {
        int which = n >> 4, h = n & 15;
        const float* Wp = (which == 0) ? Wbm : (which == 1) ? Wfd
                         : (which == 2) ? Wsd : (which == 3) ? Wfg : Wsg;
        val = __float2half_rn(Wp[k * 16 + h]);
    }
    g_gwh[n * 1024 + k] = val;
}

// ---------------- K1(+K2)/K7: fp16 cp.async GEMM, ldmatrix fragments --------
// phase 0: 1600 blocks — [0,1536) QKV (silu+head, half out), [1536,1600) gates.
// phase 1: 512 blocks — K7 plain fp32 C0.
__global__ __launch_bounds__(256, 2) void gemm_f16_kernel(
    const __half* __restrict__ A, const __half* __restrict__ WTq,
    const __half* __restrict__ WTg,
    __half* __restrict__ H0, __half* __restrict__ H1, __half* __restrict__ H2,
    float* __restrict__ Cout,
    const float* __restrict__ fdb, const float* __restrict__ sdb,
    int phase)
{
    extern __shared__ __half smh[];
    __half* As = smh;
    __half* Bs = smh + HSTG * HSTAGE;

    const int bid = blockIdx.x;
    int mode, bm, bn, z = 0;
    const __half* WT;
    __half* H = H0;
    if (phase == 0) {
        if (bid < 1536) {
            z = bid >> 9;
            int idx = bid & 511;
            bn = (idx & 7) * 128;
            bm = (idx >> 3) * 128;
            mode = 1;
            WT = WTq + (size_t)z * Dq * Dq;
            H = (z == 0) ? H0 : (z == 1) ? H1 : H2;
        } else {
            bm = (bid - 1536) * 128;
            bn = 0;
            mode = 3;
            WT = WTg;
        }
    } else {
        bn = (bid & 7) * 128;
        bm = (bid >> 3) * 128;
        mode = 0;
        WT = WTq;
    }

    const int tid = threadIdx.x;
    const int lane = tid & 31;
    const int wid = tid >> 5;
    const int gid = lane >> 2;
    const int tig = lane & 3;
    const int warpM = (wid & 1) * 64;
    const int warpN = (wid >> 1) * 32;

    const int l_r = tid >> 2;
    const int l_c = (tid & 3) * 8;

    const int a_lrow = lane & 15;
    const int a_lcol = (lane >> 4) * 8;
    const int b_lrow = ((lane >> 4) & 1) * 8 + (lane & 7);
    const int b_lcol = ((lane >> 3) & 1) * 8;

    float acc[4][4][4];
#pragma unroll
    for (int mt = 0; mt < 4; mt++)
#pragma unroll
        for (int nt = 0; nt < 4; nt++)
#pragma unroll
            for (int c = 0; c < 4; c++) acc[mt][nt][c] = 0.f;

    const __half* Ab0 = A + (size_t)(bm + l_r) * 1024 + l_c;
    const __half* Ab1 = A + (size_t)(bm + l_r + 64) * 1024 + l_c;
    const __half* Bb0 = WT + (size_t)(bn + l_r) * 1024 + l_c;
    const __half* Bb1 = WT + (size_t)(bn + l_r + 64) * 1024 + l_c;
    __half* AsD0 = As + l_r * HASTR + l_c;
    __half* AsD1 = As + (l_r + 64) * HASTR + l_c;
    __half* BsD0 = Bs + l_r * HASTR + l_c;
    __half* BsD1 = Bs + (l_r + 64) * HASTR + l_c;

    const uint32_t AsU = smem_u32(As);
    const uint32_t BsU = smem_u32(Bs);

#pragma unroll
    for (int s = 0; s < HSTG - 1; s++) {
        int k0 = s * HBK;
        cp16h(AsD0 + s * HSTAGE, Ab0 + k0);
        cp16h(AsD1 + s * HSTAGE, Ab1 + k0);
        cp16h(BsD0 + s * HSTAGE, Bb0 + k0);
        cp16h(BsD1 + s * HSTAGE, Bb1 + k0);
        asm volatile("cp.async.commit_group;");
    }

#pragma unroll 1
    for (int t = 0; t < 32; t++) {
        asm volatile("cp.async.wait_group 2;");
        __syncthreads();

        if (t + 3 < 32) {
            int s = (t + 3) & 3;
            int k0 = (t + 3) * HBK;
            cp16h(AsD0 + s * HSTAGE, Ab0 + k0);
            cp16h(AsD1 + s * HSTAGE, Ab1 + k0);
            cp16h(BsD0 + s * HSTAGE, Bb0 + k0);
            cp16h(BsD1 + s * HSTAGE, Bb1 + k0);
        }
        asm volatile("cp.async.commit_group;");

        const uint32_t AscU = AsU + (uint32_t)((t & 3) * HSTAGE) * 2u;
        const uint32_t BscU = BsU + (uint32_t)((t & 3) * HSTAGE) * 2u;
#pragma unroll
        for (int ks = 0; ks < 2; ks++) {
            const int kb = ks * 16;
            uint32_t af[4][4];
#pragma unroll
            for (int mt = 0; mt < 4; mt++) {
                uint32_t addr = AscU +
                    (uint32_t)((warpM + mt * 16 + a_lrow) * HASTR + kb + a_lcol) * 2u;
                ldsm_x4(af[mt][0], af[mt][1], af[mt][2], af[mt][3], addr);
            }
            uint32_t br[2][4];
#pragma unroll
            for (int np = 0; np < 2; np++) {
                uint32_t addr = BscU +
                    (uint32_t)((warpN + np * 16 + b_lrow) * HASTR + kb + b_lcol) * 2u;
                ldsm_x4(br[np][0], br[np][1], br[np][2], br[np][3], addr);
            }
#pragma unroll
            for (int nt = 0; nt < 4; nt++) {
                uint32_t b0 = br[nt >> 1][(nt & 1) * 2 + 0];
                uint32_t b1 = br[nt >> 1][(nt & 1) * 2 + 1];
#pragma unroll
                for (int mt = 0; mt < 4; mt++) {
                    mma_f16(acc[mt][nt][0], acc[mt][nt][1], acc[mt][nt][2], acc[mt][nt][3],
                            af[mt][0], af[mt][1], af[mt][2], af[mt][3], b0, b1);
                }
            }
        }
    }

    // epilogue
#pragma unroll
    for (int mt = 0; mt < 4; mt++) {
#pragma unroll
        for (int nt = 0; nt < 4; nt++) {
            int row = bm + warpM + mt * 16 + gid;
            int col = bn + warpN + nt * 8 + tig * 2;
#pragma unroll
            for (int half_ = 0; half_ < 2; half_++) {
                int r = row + half_ * 8;
                float v0 = acc[mt][nt][half_ * 2 + 0];
                float v1 = acc[mt][nt][half_ * 2 + 1];
                int bb = r >> 12, l = r & 4095;
                if (mode == 1) {
                    v0 = v0 * (1.f / (1.f + expf(-v0)));
                    v1 = v1 * (1.f / (1.f + expf(-v1)));
                    int h = col >> 6, hd = col & 63;
                    __half2 hv = __floats2half2_rn(v0, v1);
                    *(__half2*)(H + (((size_t)(bb * Hq + h) * Lq + l) * HDq) + hd) = hv;
                } else if (mode == 3) {
#pragma unroll
                    for (int cc = 0; cc < 2; cc++) {
                        int cl = col + cc;
                        if (cl < 80) {
                            int which = cl >> 4, h = cl & 15;
                            float s = (cc == 0) ? v0 : v1;
                            if (which == 1) s += fdb[h];
                            if (which == 2) s += sdb[h];
                            float val = sigm(s);
                            float* dst = (which == 0) ? g_beta : (which == 1) ? g_fd
                                        : (which == 2) ? g_sd : (which == 3) ? g_fg : g_sg;
                            dst[(bb * Hq + h) * Lq + l] = val;
                        }
                    }
                } else {
                    *(float2*)(Cout + (size_t)r * 1024 + col) = make_float2(v0, v1);
                }
            }
        }
    }
}

// ---------------- K4: outer products + psi/surprise + chunk decay (fused) ---
__global__ __launch_bounds__(256) void outer_kernel()
{
    __shared__ float Ks[64 * 64];
    __shared__ float Vs[64 * 64];
    __shared__ float S2[64];
    __shared__ float fdm_s[128];
    __shared__ float sdm_s[128];
    const int bhn = blockIdx.x;
    const int bh = bhn / NCH, n = bhn % NCH;
    const int t = threadIdx.x;
    const int d0 = (t & 15) * 4;
    const int e0 = (t >> 4) * 4;
    const int posbase = bh * Lq + n * CH;

    float af[4][4], as_[4][4];
#pragma unroll
    for (int i = 0; i < 4; i++)
#pragma unroll
        for (int j = 0; j < 4; j++) { af[i][j] = 0.f; as_[i][j] = 0.f; }

    for (int half_ = 0; half_ < 2; half_++) {
        size_t base = ((size_t)(posbase + half_ * 64)) * HDq;
        // fill smem with beta-scaled k,v (half source: 8 halves per iter)
        for (int i = t; i < 512; i += 256) {
            int row = i >> 3;
            float b = g_beta[posbase + half_ * 64 + row];
            uint4 kr = ((const uint4*)(g_k + base))[i];
            uint4 vr = ((const uint4*)(g_v + base))[i];
            float* kd = &Ks[i * 8];
            float* vd = &Vs[i * 8];
            const __half2* kh = (const __half2*)&kr;
            const __half2* vh = (const __half2*)&vr;
#pragma unroll
            for (int j = 0; j < 4; j++) {
                float2 kf = __half22float2(kh[j]);
                float2 vf = __half22float2(vh[j]);
                kd[j * 2 + 0] = kf.x * b; kd[j * 2 + 1] = kf.y * b;
                vd[j * 2 + 0] = vf.x * b; vd[j * 2 + 1] = vf.y * b;
            }
        }
        __syncthreads();

        {
            int r = t >> 2, q = t & 3;
            const float4* krow = (const float4*)&Ks[r * 64 + q * 16];
            const float4* vrow = (const float4*)&Vs[r * 64 + q * 16];
            float kk = 0.f, vv = 0.f, kv = 0.f;
#pragma unroll
            for (int j = 0; j < 4; j++) {
                float4 a = krow[j], b = vrow[j];
                kk += a.x * a.x + a.y * a.y + a.z * a.z + a.w * a.w;
                vv += b.x * b.x + b.y * b.y + b.z * b.z + b.w * b.w;
                kv += a.x * b.x + a.y * b.y + a.z * b.z + a.w * b.w;
            }
            kk += __shfl_xor_sync(0xffffffffu, kk, 1);
            kk += __shfl_xor_sync(0xffffffffu, kk, 2);
            vv += __shfl_xor_sync(0xffffffffu, vv, 1);
            vv += __shfl_xor_sync(0xffffffffu, vv, 2);
            kv += __shfl_xor_sync(0xffffffffu, kv, 1);
            kv += __shfl_xor_sync(0xffffffffu, kv, 2);
            if (q == 0) {
                float kn = sqrtf(kk) + 1e-8f;
                float vn = sqrtf(vv) + 1e-8f;
                float praw = fabsf(kv) / (kn * vn);
                float psi = sigm(3.f * praw);
                float sur = sigm((psi - 0.5f) * 10.f);
                S2[r] = sur * sur;
                int p = posbase + half_ * 64 + r;
                g_psi[p] = psi;
                fdm_s[half_ * 64 + r] = g_fd[p] * (1.f - 0.1f * psi);
                sdm_s[half_ * 64 + r] = g_sd[p] * (1.f - 0.05f * psi);
            }
        }
        __syncthreads();

#pragma unroll 4
        for (int l = 0; l < 64; l++) {
            float4 vv4 = *(float4*)&Vs[l * 64 + d0];
            float4 kk4 = *(float4*)&Ks[l * 64 + e0];
            float s2 = S2[l];
            float v[4] = {vv4.x, vv4.y, vv4.z, vv4.w};
            float k[4] = {kk4.x, kk4.y, kk4.z, kk4.w};
            float vs[4] = {v[0] * s2, v[1] * s2, v[2] * s2, v[3] * s2};
#pragma unroll
            for (int i = 0; i < 4; i++)
#pragma unroll
                for (int j = 0; j < 4; j++) {
                    af[i][j] += v[i] * k[j];
                    as_[i][j] += vs[i] * k[j];
                }
        }
        __syncthreads();
    }

    if (t < 32) {
        float f = 0.f, s = 0.f;
#pragma unroll
        for (int j = t; j < 128; j += 32) { f += fdm_s[j]; s += sdm_s[j]; }
#pragma unroll
        for (int off = 16; off; off >>= 1) {
            f += __shfl_xor_sync(0xffffffffu, f, off);
            s += __shfl_xor_sync(0xffffffffu, s, off);
        }
        if (t == 0) {
            float gf = f * (1.f / 128.f), gs = s * (1.f / 128.f);
#pragma unroll
            for (int i = 0; i < 7; i++) { gf *= gf; gs *= gs; }
            g_gf[bhn] = gf;
            g_gs[bhn] = gs;
        }
    }

    size_t abase = (size_t)bhn * 4096;
#pragma unroll
    for (int i = 0; i < 4; i++) {
        *(float4*)&g_Af[abase + (d0 + i) * 64 + e0] =
            make_float4(af[i][0], af[i][1], af[i][2], af[i][3]);
        *(float4*)&g_As[abase + (d0 + i) * 64 + e0] =
            make_float4(as_[i][0], as_[i][1], as_[i][2], as_[i][3]);
    }
}

// ---------------- K5: decayed prefix scan over chunks (in-place) ------------
__global__ void scan_kernel()
{
    int bh = blockIdx.x >> 4;
    int eb = blockIdx.x & 15;
    int entry = eb * 256 + threadIdx.x;
    float sfv = 0.f, ssv = 0.f;
#pragma unroll 1
    for (int n = 0; n < NCH; n++) {
        int bhn = bh * NCH + n;
        float gf = g_gf[bhn], gs = g_gs[bhn];
        size_t idx = (size_t)bhn * 4096 + entry;
        sfv = sfv * gf + g_Af[idx]; g_Af[idx] = sfv;
        ssv = ssv * gs + g_As[idx]; g_As[idx] = ssv;
    }
}

// ---------------- K6: O = Q @ S (fast+slow), gate/alpha mix -> omix (half) --
__global__ __launch_bounds__(256) void outmix_kernel()
{
    __shared__ float Sf[4096];
    __shared__ float Ss[4096];
    __shared__ float Qs[32 * 64];
    __shared__ float gA[32], gB[32];
    const int bhn = blockIdx.x;
    const int bh = bhn / NCH, n = bhn % NCH;
    const int b = bh >> 4, h = bh & 15;
    const int t = threadIdx.x;

    size_t abase = (size_t)bhn * 4096;
    for (int i = t; i < 1024; i += 256) {
        ((float4*)Sf)[i] = ((const float4*)(g_Af + abase))[i];
        ((float4*)Ss)[i] = ((const float4*)(g_As + abase))[i];
    }

    const int d = t & 63;
    const int lb = (t >> 6) * 8;

    for (int pass = 0; pass < 4; pass++) {
        int l0 = pass * 32;
        size_t qbase = ((size_t)bh * Lq + n * CH + l0) * HDq;
        // Qs fill from half q: 2048 floats = 256 x 8 halves
        for (int i = t; i < 256; i += 256) {
            uint4 qr = ((const uint4*)(g_q + qbase))[i];
            const __half2* qh = (const __half2*)&qr;
            float* qd = &Qs[i * 8];
#pragma unroll
            for (int j = 0; j < 4; j++) {
                float2 qf = __half22float2(qh[j]);
                qd[j * 2 + 0] = qf.x;
                qd[j * 2 + 1] = qf.y;
            }
        }
        if (t < 32) {
            int p = bh * Lq + n * CH + l0 + t;
            float psi = g_psi[p];
            float alpha = 0.5f + 0.3f * psi;
            gA[t] = alpha * g_fg[p];
            gB[t] = (1.f - alpha) * g_sg[p];
        }
        __syncthreads();

        float accf[8], accs[8];
#pragma unroll
        for (int l = 0; l < 8; l++) { accf[l] = 0.f; accs[l] = 0.f; }
#pragma unroll 8
        for (int e = 0; e < 64; e += 2) {
            float sf0 = Sf[e * 64 + d];
            float sf1 = Sf[(e + 1) * 64 + d];
            float ss0 = Ss[e * 64 + d];
            float ss1 = Ss[(e + 1) * 64 + d];
#pragma unroll
            for (int l = 0; l < 8; l++) {
                float2 q2 = *(float2*)&Qs[(lb + l) * 64 + e];
                accf[l] += q2.x * sf0 + q2.y * sf1;
                accs[l] += q2.x * ss0 + q2.y * ss1;
            }
        }
#pragma unroll
        for (int l = 0; l < 8; l++) {
            int ll = lb + l;
            float val = gA[ll] * accf[l] + gB[ll] * accs[l];
            int lglob = n * CH + l0 + ll;
            g_omixh[((size_t)b * Lq + lglob) * Dq + h * HDq + d] = __float2half_rn(val);
        }
        __syncthreads();
    }
}

// ---------------- launch ----------------
extern "C" void kernel_launch(void* const* d_in, const int* in_sizes, int n_in,
                              void* d_out, int out_size)
{
    const float* x   = (const float*)d_in[0];
    const float* Wq  = (const float*)d_in[1];
    const float* Wk  = (const float*)d_in[2];
    const float* Wv  = (const float*)d_in[3];
    const float* Wb  = (const float*)d_in[4];
    const float* Wfd = (const float*)d_in[5];
    const float* fdb = (const float*)d_in[6];
    const float* Wsd = (const float*)d_in[7];
    const float* sdb = (const float*)d_in[8];
    const float* Wfg = (const float*)d_in[9];
    const float* Wsg = (const float*)d_in[10];
    const float* Wo  = (const float*)d_in[11];
    float* out = (float*)d_out;

    void *p_q = nullptr, *p_k = nullptr, *p_v = nullptr;
    void *p_xh = nullptr, *p_wh = nullptr, *p_gwh = nullptr, *p_oh = nullptr;
    cudaGetSymbolAddress(&p_q, g_q);
    cudaGetSymbolAddress(&p_k, g_k);
    cudaGetSymbolAddress(&p_v, g_v);
    cudaGetSymbolAddress(&p_xh, g_xh);
    cudaGetSymbolAddress(&p_wh, g_wh);
    cudaGetSymbolAddress(&p_gwh, g_gwh);
    cudaGetSymbolAddress(&p_oh, g_omixh);

    cudaFuncSetAttribute(gemm_f16_kernel,
                         cudaFuncAttributeMaxDynamicSharedMemorySize, HSMEM);

    // K0: conversions & packing
    xhalf_kernel<<<4096, 256>>>(x);
    wtrans_kernel<<<dim3(32, 32, 4), dim3(32, 8)>>>(Wq, Wk, Wv, Wo);
    gwpack_kernel<<<512, 256>>>(Wb, Wfd, Wsd, Wfg, Wsg);

    // K1+K2: fused QKV + gate projections (1600 blocks), half q/k/v out
    gemm_f16_kernel<<<1600, 256, HSMEM>>>(
        (const __half*)p_xh, (const __half*)p_wh, (const __half*)p_gwh,
        (__half*)p_q, (__half*)p_k, (__half*)p_v, nullptr, fdb, sdb, 0);

    // K4: fused outer products + psi/surprise + chunk decay
    outer_kernel<<<Bq * Hq * NCH, 256>>>();

    // K5: decayed scan across chunks
    scan_kernel<<<Bq * Hq * 16, 256>>>();

    // K6: per-chunk output + gate mixing (half omix)
    outmix_kernel<<<Bq * Hq * NCH, 256>>>();

    // K7: output projection (512 blocks, fp32 out)
    gemm_f16_kernel<<<512, 256, HSMEM>>>(
        (const __half*)p_oh, (const __half*)p_wh + (size_t)3 * Dq * Dq,
        (const __half*)p_gwh, nullptr, nullptr, nullptr, out, fdb, sdb, 1);
}

// round 13
// speedup vs baseline: 1.4497x; 1.0936x over previous
#include <cuda_runtime.h>
#include <cuda_fp16.h>
#include <math.h>
#include <stdint.h>

#define Bq 2
#define Lq 4096
#define Dq 1024
#define Hq 16
#define HDq 64
#define NCH 32
#define CH 128
#define BHL (Bq*Hq*Lq)

// ---- fp16 cp.async GEMM geometry (proven config) ----
#define HSTG 4
#define HBK 32
#define HASTR 40
#define HSTAGE (128*HASTR)
#define HSMEM (HSTG*2*HSTAGE*2)

// ---------------- device scratch (no allocations allowed) ----------------
__device__ __half g_xh[Bq*Lq*Dq];         // half x [8192][1024]
__device__ __half g_wh[4*Dq*Dq];          // W^T [n][k] for Wq,Wk,Wv,Wo
__device__ __half g_gwh[128*Dq];          // packed gate weights^T
__device__ __half g_omixh[Bq*Lq*Dq];
__device__ __half g_q[Bq*Hq*Lq*HDq];      // half q (silu)
__device__ __half g_k[Bq*Hq*Lq*HDq];      // half k (silu, no beta)
__device__ __half g_v[Bq*Hq*Lq*HDq];      // half v (silu, no beta)
__device__ float g_beta[BHL];
__device__ float g_fd[BHL];
__device__ float g_sd[BHL];
__device__ float g_fg[BHL];
__device__ float g_sg[BHL];
__device__ float g_psi[BHL];
__device__ float g_gf[Bq*Hq*NCH];
__device__ float g_gs[Bq*Hq*NCH];
__device__ float g_Af[Bq*Hq*NCH*HDq*HDq];
__device__ float g_As[Bq*Hq*NCH*HDq*HDq];

__device__ __forceinline__ float sigm(float x) { return 1.f / (1.f + expf(-x)); }

__device__ __forceinline__ uint32_t smem_u32(const void* p) {
    return (uint32_t)__cvta_generic_to_shared(p);
}

__device__ __forceinline__ void cp16h(__half* dst, const __half* src) {
    uint32_t d = (uint32_t)__cvta_generic_to_shared(dst);
    asm volatile("cp.async.cg.shared.global [%0], [%1], 16;" :: "r"(d), "l"(src));
}

__device__ __forceinline__ void ldsm_x4(
    uint32_t& r0, uint32_t& r1, uint32_t& r2, uint32_t& r3, uint32_t addr)
{
    asm volatile("ldmatrix.sync.aligned.m8n8.x4.shared.b16 {%0,%1,%2,%3}, [%4];"
        : "=r"(r0), "=r"(r1), "=r"(r2), "=r"(r3) : "r"(addr));
}

// fp16 k16 mma, f32 accum
__device__ __forceinline__ void mma_f16(
    float& c0, float& c1, float& c2, float& c3,
    uint32_t a0, uint32_t a1, uint32_t a2, uint32_t a3,
    uint32_t b0, uint32_t b1)
{
    asm volatile(
        "mma.sync.aligned.m16n8k16.row.col.f32.f16.f16.f32 "
        "{%0,%1,%2,%3}, {%4,%5,%6,%7}, {%8,%9}, {%0,%1,%2,%3};"
        : "+f"(c0), "+f"(c1), "+f"(c2), "+f"(c3)
        : "r"(a0), "r"(a1), "r"(a2), "r"(a3), "r"(b0), "r"(b1));
}

// ---------------- K0: fused conversions/packing (8704 blocks) ---------------
// [0,4096):    x -> half
// [4096,8192): W -> half transposed [n][k]
// [8192,8704): pack gate weights
__global__ __launch_bounds__(256) void prep0_kernel(
    const float* __restrict__ x,
    const float* __restrict__ Wq, const float* __restrict__ Wk,
    const float* __restrict__ Wv, const float* __restrict__ Wo,
    const float* __restrict__ Wbm, const float* __restrict__ Wfd,
    const float* __restrict__ Wsd, const float* __restrict__ Wfg,
    const float* __restrict__ Wsg)
{
    __shared__ __half tile[32][33];
    const int bid = blockIdx.x;
    const int tid = threadIdx.x;

    if (bid < 4096) {
        size_t i = (size_t)bid * 256 + tid;
        const float4* s = (const float4*)x;
        float4 v0 = s[i * 2], v1 = s[i * 2 + 1];
        __half2 h0 = __floats2half2_rn(v0.x, v0.y);
        __half2 h1 = __floats2half2_rn(v0.z, v0.w);
        __half2 h2 = __floats2half2_rn(v1.x, v1.y);
        __half2 h3 = __floats2half2_rn(v1.z, v1.w);
        uint4 o;
        o.x = *(uint32_t*)&h0; o.y = *(uint32_t*)&h1;
        o.z = *(uint32_t*)&h2; o.w = *(uint32_t*)&h3;
        ((uint4*)g_xh)[i] = o;
    } else if (bid < 8192) {
        int idx = bid - 4096;
        int z = idx >> 10;
        int xy = idx & 1023;
        const float* W = (z == 0) ? Wq : (z == 1) ? Wk : (z == 2) ? Wv : Wo;
        __half* WT = g_wh + (size_t)z * Dq * Dq;
        int x0 = (xy & 31) * 32;
        int y0 = (xy >> 5) * 32;
        int tx = tid & 31, ty = tid >> 5;   // ty 0..7
#pragma unroll
        for (int i = 0; i < 4; i++)
            tile[ty + 8 * i][tx] = __float2half_rn(W[(size_t)(y0 + ty + 8 * i) * 1024 + x0 + tx]);
        __syncthreads();
#pragma unroll
        for (int i = 0; i < 4; i++)
            WT[(size_t)(x0 + ty + 8 * i) * 1024 + y0 + tx] = tile[tx][ty + 8 * i];
    } else {
        int idx = (bid - 8192) * 256 + tid;
        int n = idx >> 10, k = idx & 1023;
        __half val = __float2half_rn(0.f);
        if (n < 80) {
            int which = n >> 4, h = n & 15;
            const float* Wp = (which == 0) ? Wbm : (which == 1) ? Wfd
                             : (which == 2) ? Wsd : (which == 3) ? Wfg : Wsg;
            val = __float2half_rn(Wp[k * 16 + h]);
        }
        g_gwh[n * 1024 + k] = val;
    }
}

// ---------------- K1(+K2)/K7: fp16 cp.async GEMM, ldmatrix fragments --------
// phase 0: 1600 blocks — [0,1536) QKV (silu+head, half out), [1536,1600) gates.
// phase 1: 512 blocks — K7 plain fp32 Cout.
__global__ __launch_bounds__(256, 2) void gemm_f16_kernel(
    const __half* __restrict__ A, const __half* __restrict__ WTq,
    const __half* __restrict__ WTg,
    __half* __restrict__ H0, __half* __restrict__ H1, __half* __restrict__ H2,
    float* __restrict__ Cout,
    const float* __restrict__ fdb, const float* __restrict__ sdb,
    int phase)
{
    extern __shared__ __half smh[];
    __half* As = smh;
    __half* Bs = smh + HSTG * HSTAGE;

    const int bid = blockIdx.x;
    int mode, bm, bn, z = 0;
    const __half* WT;
    __half* H = H0;
    if (phase == 0) {
        if (bid < 1536) {
            z = bid >> 9;
            int idx = bid & 511;
            bn = (idx & 7) * 128;
            bm = (idx >> 3) * 128;
            mode = 1;
            WT = WTq + (size_t)z * Dq * Dq;
            H = (z == 0) ? H0 : (z == 1) ? H1 : H2;
        } else {
            bm = (bid - 1536) * 128;
            bn = 0;
            mode = 3;
            WT = WTg;
        }
    } else {
        bn = (bid & 7) * 128;
        bm = (bid >> 3) * 128;
        mode = 0;
        WT = WTq;
    }

    const int tid = threadIdx.x;
    const int lane = tid & 31;
    const int wid = tid >> 5;
    const int gid = lane >> 2;
    const int tig = lane & 3;
    const int warpM = (wid & 1) * 64;
    const int warpN = (wid >> 1) * 32;

    const int l_r = tid >> 2;
    const int l_c = (tid & 3) * 8;

    const int a_lrow = lane & 15;
    const int a_lcol = (lane >> 4) * 8;
    const int b_lrow = ((lane >> 4) & 1) * 8 + (lane & 7);
    const int b_lcol = ((lane >> 3) & 1) * 8;

    float acc[4][4][4];
#pragma unroll
    for (int mt = 0; mt < 4; mt++)
#pragma unroll
        for (int nt = 0; nt < 4; nt++)
#pragma unroll
            for (int c = 0; c < 4; c++) acc[mt][nt][c] = 0.f;

    const __half* Ab0 = A + (size_t)(bm + l_r) * 1024 + l_c;
    const __half* Ab1 = A + (size_t)(bm + l_r + 64) * 1024 + l_c;
    const __half* Bb0 = WT + (size_t)(bn + l_r) * 1024 + l_c;
    const __half* Bb1 = WT + (size_t)(bn + l_r + 64) * 1024 + l_c;
    __half* AsD0 = As + l_r * HASTR + l_c;
    __half* AsD1 = As + (l_r + 64) * HASTR + l_c;
    __half* BsD0 = Bs + l_r * HASTR + l_c;
    __half* BsD1 = Bs + (l_r + 64) * HASTR + l_c;

    const uint32_t AsU = smem_u32(As);
    const uint32_t BsU = smem_u32(Bs);

#pragma unroll
    for (int s = 0; s < HSTG - 1; s++) {
        int k0 = s * HBK;
        cp16h(AsD0 + s * HSTAGE, Ab0 + k0);
        cp16h(AsD1 + s * HSTAGE, Ab1 + k0);
        cp16h(BsD0 + s * HSTAGE, Bb0 + k0);
        cp16h(BsD1 + s * HSTAGE, Bb1 + k0);
        asm volatile("cp.async.commit_group;");
    }

#pragma unroll 1
    for (int t = 0; t < 32; t++) {
        asm volatile("cp.async.wait_group 2;");
        __syncthreads();

        const uint32_t AscU = AsU + (uint32_t)((t & 3) * HSTAGE) * 2u;
        const uint32_t BscU = BsU + (uint32_t)((t & 3) * HSTAGE) * 2u;

        // hoisted LDSM for ks=0 — overlaps with cp.async issue below
        uint32_t af[4][4];
        uint32_t br[2][4];
#pragma unroll
        for (int mt = 0; mt < 4; mt++) {
            uint32_t addr = AscU +
                (uint32_t)((warpM + mt * 16 + a_lrow) * HASTR + a_lcol) * 2u;
            ldsm_x4(af[mt][0], af[mt][1], af[mt][2], af[mt][3], addr);
        }
#pragma unroll
        for (int np = 0; np < 2; np++) {
            uint32_t addr = BscU +
                (uint32_t)((warpN + np * 16 + b_lrow) * HASTR + b_lcol) * 2u;
            ldsm_x4(br[np][0], br[np][1], br[np][2], br[np][3], addr);
        }

        if (t + 3 < 32) {
            int s = (t + 3) & 3;
            int k0 = (t + 3) * HBK;
            cp16h(AsD0 + s * HSTAGE, Ab0 + k0);
            cp16h(AsD1 + s * HSTAGE, Ab1 + k0);
            cp16h(BsD0 + s * HSTAGE, Bb0 + k0);
            cp16h(BsD1 + s * HSTAGE, Bb1 + k0);
        }
        asm volatile("cp.async.commit_group;");

        // mma ks=0
#pragma unroll
        for (int nt = 0; nt < 4; nt++) {
            uint32_t b0 = br[nt >> 1][(nt & 1) * 2 + 0];
            uint32_t b1 = br[nt >> 1][(nt & 1) * 2 + 1];
#pragma unroll
            for (int mt = 0; mt < 4; mt++) {
                mma_f16(acc[mt][nt][0], acc[mt][nt][1], acc[mt][nt][2], acc[mt][nt][3],
                        af[mt][0], af[mt][1], af[mt][2], af[mt][3], b0, b1);
            }
        }

        // ks=1: reload frags (reuse regs), mma
#pragma unroll
        for (int mt = 0; mt < 4; mt++) {
            uint32_t addr = AscU +
                (uint32_t)((warpM + mt * 16 + a_lrow) * HASTR + 16 + a_lcol) * 2u;
            ldsm_x4(af[mt][0], af[mt][1], af[mt][2], af[mt][3], addr);
        }
#pragma unroll
        for (int np = 0; np < 2; np++) {
            uint32_t addr = BscU +
                (uint32_t)((warpN + np * 16 + b_lrow) * HASTR + 16 + b_lcol) * 2u;
            ldsm_x4(br[np][0], br[np][1], br[np][2], br[np][3], addr);
        }
#pragma unroll
        for (int nt = 0; nt < 4; nt++) {
            uint32_t b0 = br[nt >> 1][(nt & 1) * 2 + 0];
            uint32_t b1 = br[nt >> 1][(nt & 1) * 2 + 1];
#pragma unroll
            for (int mt = 0; mt < 4; mt++) {
                mma_f16(acc[mt][nt][0], acc[mt][nt][1], acc[mt][nt][2], acc[mt][nt][3],
                        af[mt][0], af[mt][1], af[mt][2], af[mt][3], b0, b1);
            }
        }
    }

    // epilogue
#pragma unroll
    for (int mt = 0; mt < 4; mt++) {
#pragma unroll
        for (int nt = 0; nt < 4; nt++) {
            int row = bm + warpM + mt * 16 + gid;
            int col = bn + warpN + nt * 8 + tig * 2;
#pragma unroll
            for (int half_ = 0; half_ < 2; half_++) {
                int r = row + half_ * 8;
                float v0 = acc[mt][nt][half_ * 2 + 0];
                float v1 = acc[mt][nt][half_ * 2 + 1];
                int bb = r >> 12, l = r & 4095;
                if (mode == 1) {
                    v0 = v0 * (1.f / (1.f + expf(-v0)));
                    v1 = v1 * (1.f / (1.f + expf(-v1)));
                    int h = col >> 6, hd = col & 63;
                    __half2 hv = __floats2half2_rn(v0, v1);
                    *(__half2*)(H + (((size_t)(bb * Hq + h) * Lq + l) * HDq) + hd) = hv;
                } else if (mode == 3) {
#pragma unroll
                    for (int cc = 0; cc < 2; cc++) {
                        int cl = col + cc;
                        if (cl < 80) {
                            int which = cl >> 4, h = cl & 15;
                            float s = (cc == 0) ? v0 : v1;
                            if (which == 1) s += fdb[h];
                            if (which == 2) s += sdb[h];
                            float val = sigm(s);
                            float* dst = (which == 0) ? g_beta : (which == 1) ? g_fd
                                        : (which == 2) ? g_sd : (which == 3) ? g_fg : g_sg;
                            dst[(bb * Hq + h) * Lq + l] = val;
                        }
                    }
                } else {
                    *(float2*)(Cout + (size_t)r * 1024 + col) = make_float2(v0, v1);
                }
            }
        }
    }
}

// ---------------- K4: outer products + psi/surprise + chunk decay (fused) ---
__global__ __launch_bounds__(256) void outer_kernel()
{
    __shared__ float Ks[64 * 64];
    __shared__ float Vs[64 * 64];
    __shared__ float S2[64];
    __shared__ float fdm_s[128];
    __shared__ float sdm_s[128];
    const int bhn = blockIdx.x;
    const int bh = bhn / NCH, n = bhn % NCH;
    const int t = threadIdx.x;
    const int d0 = (t & 15) * 4;
    const int e0 = (t >> 4) * 4;
    const int posbase = bh * Lq + n * CH;

    float af[4][4], as_[4][4];
#pragma unroll
    for (int i = 0; i < 4; i++)
#pragma unroll
        for (int j = 0; j < 4; j++) { af[i][j] = 0.f; as_[i][j] = 0.f; }

    for (int half_ = 0; half_ < 2; half_++) {
        size_t base = ((size_t)(posbase + half_ * 64)) * HDq;
        for (int i = t; i < 512; i += 256) {
            int row = i >> 3;
            float b = g_beta[posbase + half_ * 64 + row];
            uint4 kr = ((const uint4*)(g_k + base))[i];
            uint4 vr = ((const uint4*)(g_v + base))[i];
            float* kd = &Ks[i * 8];
            float* vd = &Vs[i * 8];
            const __half2* kh = (const __half2*)&kr;
            const __half2* vh = (const __half2*)&vr;
#pragma unroll
            for (int j = 0; j < 4; j++) {
                float2 kf = __half22float2(kh[j]);
                float2 vf = __half22float2(vh[j]);
                kd[j * 2 + 0] = kf.x * b; kd[j * 2 + 1] = kf.y * b;
                vd[j * 2 + 0] = vf.x * b; vd[j * 2 + 1] = vf.y * b;
            }
        }
        __syncthreads();

        {
            int r = t >> 2, q = t & 3;
            const float4* krow = (const float4*)&Ks[r * 64 + q * 16];
            const float4* vrow = (const float4*)&Vs[r * 64 + q * 16];
            float kk = 0.f, vv = 0.f, kv = 0.f;
#pragma unroll
            for (int j = 0; j < 4; j++) {
                float4 a = krow[j], b = vrow[j];
                kk += a.x * a.x + a.y * a.y + a.z * a.z + a.w * a.w;
                vv += b.x * b.x + b.y * b.y + b.z * b.z + b.w * b.w;
                kv += a.x * b.x + a.y * b.y + a.z * b.z + a.w * b.w;
            }
            kk += __shfl_xor_sync(0xffffffffu, kk, 1);
            kk += __shfl_xor_sync(0xffffffffu, kk, 2);
            vv += __shfl_xor_sync(0xffffffffu, vv, 1);
            vv += __shfl_xor_sync(0xffffffffu, vv, 2);
            kv += __shfl_xor_sync(0xffffffffu, kv, 1);
            kv += __shfl_xor_sync(0xffffffffu, kv, 2);
            if (q == 0) {
                float kn = sqrtf(kk) + 1e-8f;
                float vn = sqrtf(vv) + 1e-8f;
                float praw = fabsf(kv) / (kn * vn);
                float psi = sigm(3.f * praw);
                float sur = sigm((psi - 0.5f) * 10.f);
                S2[r] = sur * sur;
                int p = posbase + half_ * 64 + r;
                g_psi[p] = psi;
                fdm_s[half_ * 64 + r] = g_fd[p] * (1.f - 0.1f * psi);
                sdm_s[half_ * 64 + r] = g_sd[p] * (1.f - 0.05f * psi);
            }
        }
        __syncthreads();

#pragma unroll 4
        for (int l = 0; l < 64; l++) {
            float4 vv4 = *(float4*)&Vs[l * 64 + d0];
            float4 kk4 = *(float4*)&Ks[l * 64 + e0];
            float s2 = S2[l];
            float v[4] = {vv4.x, vv4.y, vv4.z, vv4.w};
            float k[4] = {kk4.x, kk4.y, kk4.z, kk4.w};
            float vs[4] = {v[0] * s2, v[1] * s2, v[2] * s2, v[3] * s2};
#pragma unroll
            for (int i = 0; i < 4; i++)
#pragma unroll
                for (int j = 0; j < 4; j++) {
                    af[i][j] += v[i] * k[j];
                    as_[i][j] += vs[i] * k[j];
                }
        }
        __syncthreads();
    }

    if (t < 32) {
        float f = 0.f, s = 0.f;
#pragma unroll
        for (int j = t; j < 128; j += 32) { f += fdm_s[j]; s += sdm_s[j]; }
#pragma unroll
        for (int off = 16; off; off >>= 1) {
            f += __shfl_xor_sync(0xffffffffu, f, off);
            s += __shfl_xor_sync(0xffffffffu, s, off);
        }
        if (t == 0) {
            float gf = f * (1.f / 128.f), gs = s * (1.f / 128.f);
#pragma unroll
            for (int i = 0; i < 7; i++) { gf *= gf; gs *= gs; }
            g_gf[bhn] = gf;
            g_gs[bhn] = gs;
        }
    }

    size_t abase = (size_t)bhn * 4096;
#pragma unroll
    for (int i = 0; i < 4; i++) {
        *(float4*)&g_Af[abase + (d0 + i) * 64 + e0] =
            make_float4(af[i][0], af[i][1], af[i][2], af[i][3]);
        *(float4*)&g_As[abase + (d0 + i) * 64 + e0] =
            make_float4(as_[i][0], as_[i][1], as_[i][2], as_[i][3]);
    }
}

// ---------------- K5: decayed prefix scan over chunks (in-place) ------------
__global__ void scan_kernel()
{
    int bh = blockIdx.x >> 4;
    int eb = blockIdx.x & 15;
    int entry = eb * 256 + threadIdx.x;
    float sfv = 0.f, ssv = 0.f;
#pragma unroll 1
    for (int n = 0; n < NCH; n++) {
        int bhn = bh * NCH + n;
        float gf = g_gf[bhn], gs = g_gs[bhn];
        size_t idx = (size_t)bhn * 4096 + entry;
        sfv = sfv * gf + g_Af[idx]; g_Af[idx] = sfv;
        ssv = ssv * gs + g_As[idx]; g_As[idx] = ssv;
    }
}

// ---------------- K6: O = Q @ S (fast+slow), gate/alpha mix -> omix (half) --
__global__ __launch_bounds__(256) void outmix_kernel()
{
    __shared__ float Sf[4096];
    __shared__ float Ss[4096];
    __shared__ float Qs[32 * 64];
    __shared__ float gA[32], gB[32];
    const int bhn = blockIdx.x;
    const int bh = bhn / NCH, n = bhn % NCH;
    const int b = bh >> 4, h = bh & 15;
    const int t = threadIdx.x;

    size_t abase = (size_t)bhn * 4096;
    for (int i = t; i < 1024; i += 256) {
        ((float4*)Sf)[i] = ((const float4*)(g_Af + abase))[i];
        ((float4*)Ss)[i] = ((const float4*)(g_As + abase))[i];
    }

    const int d = t & 63;
    const int lb = (t >> 6) * 8;

    for (int pass = 0; pass < 4; pass++) {
        int l0 = pass * 32;
        size_t qbase = ((size_t)bh * Lq + n * CH + l0) * HDq;
        for (int i = t; i < 256; i += 256) {
            uint4 qr = ((const uint4*)(g_q + qbase))[i];
            const __half2* qh = (const __half2*)&qr;
            float* qd = &Qs[i * 8];
#pragma unroll
            for (int j = 0; j < 4; j++) {
                float2 qf = __half22float2(qh[j]);
                qd[j * 2 + 0] = qf.x;
                qd[j * 2 + 1] = qf.y;
            }
        }
        if (t < 32) {
            int p = bh * Lq + n * CH + l0 + t;
            float psi = g_psi[p];
            float alpha = 0.5f + 0.3f * psi;
            gA[t] = alpha * g_fg[p];
            gB[t] = (1.f - alpha) * g_sg[p];
        }
        __syncthreads();

        float accf[8], accs[8];
#pragma unroll
        for (int l = 0; l < 8; l++) { accf[l] = 0.f; accs[l] = 0.f; }
#pragma unroll 8
        for (int e = 0; e < 64; e += 2) {
            float sf0 = Sf[e * 64 + d];
            float sf1 = Sf[(e + 1) * 64 + d];
            float ss0 = Ss[e * 64 + d];
            float ss1 = Ss[(e + 1) * 64 + d];
#pragma unroll
            for (int l = 0; l < 8; l++) {
                float2 q2 = *(float2*)&Qs[(lb + l) * 64 + e];
                accf[l] += q2.x * sf0 + q2.y * sf1;
                accs[l] += q2.x * ss0 + q2.y * ss1;
            }
        }
#pragma unroll
        for (int l = 0; l < 8; l++) {
            int ll = lb + l;
            float val = gA[ll] * accf[l] + gB[ll] * accs[l];
            int lglob = n * CH + l0 + ll;
            g_omixh[((size_t)b * Lq + lglob) * Dq + h * HDq + d] = __float2half_rn(val);
        }
        __syncthreads();
    }
}

// ---------------- launch ----------------
extern "C" void kernel_launch(void* const* d_in, const int* in_sizes, int n_in,
                              void* d_out, int out_size)
{
    const float* x   = (const float*)d_in[0];
    const float* Wq  = (const float*)d_in[1];
    const float* Wk  = (const float*)d_in[2];
    const float* Wv  = (const float*)d_in[3];
    const float* Wb  = (const float*)d_in[4];
    const float* Wfd = (const float*)d_in[5];
    const float* fdb = (const float*)d_in[6];
    const float* Wsd = (const float*)d_in[7];
    const float* sdb = (const float*)d_in[8];
    const float* Wfg = (const float*)d_in[9];
    const float* Wsg = (const float*)d_in[10];
    const float* Wo  = (const float*)d_in[11];
    float* out = (float*)d_out;

    void *p_q = nullptr, *p_k = nullptr, *p_v = nullptr;
    void *p_xh = nullptr, *p_wh = nullptr, *p_gwh = nullptr, *p_oh = nullptr;
    cudaGetSymbolAddress(&p_q, g_q);
    cudaGetSymbolAddress(&p_k, g_k);
    cudaGetSymbolAddress(&p_v, g_v);
    cudaGetSymbolAddress(&p_xh, g_xh);
    cudaGetSymbolAddress(&p_wh, g_wh);
    cudaGetSymbolAddress(&p_gwh, g_gwh);
    cudaGetSymbolAddress(&p_oh, g_omixh);

    cudaFuncSetAttribute(gemm_f16_kernel,
                         cudaFuncAttributeMaxDynamicSharedMemorySize, HSMEM);

    // K0: fused conversions & packing
    prep0_kernel<<<8704, 256>>>(x, Wq, Wk, Wv, Wo, Wb, Wfd, Wsd, Wfg, Wsg);

    // K1+K2: fused QKV + gate projections (1600 blocks), half q/k/v out
    gemm_f16_kernel<<<1600, 256, HSMEM>>>(
        (const __half*)p_xh, (const __half*)p_wh, (const __half*)p_gwh,
        (__half*)p_q, (__half*)p_k, (__half*)p_v, nullptr, fdb, sdb, 0);

    // K4: fused outer products + psi/surprise + chunk decay
    outer_kernel<<<Bq * Hq * NCH, 256>>>();

    // K5: decayed scan across chunks
    scan_kernel<<<Bq * Hq * 16, 256>>>();

    // K6: per-chunk output + gate mixing (half omix)
    outmix_kernel<<<Bq * Hq * NCH, 256>>>();

    // K7: output projection (512 blocks, fp32 out)
    gemm_f16_kernel<<<512, 256, HSMEM>>>(
        (const __half*)p_oh, (const __half*)p_wh + (size_t)3 * Dq * Dq,
        (const __half*)p_gwh, nullptr, nullptr, nullptr, out, fdb, sdb, 1);
}

// round 14
// speedup vs baseline: 1.4892x; 1.0273x over previous
#include <cuda_runtime.h>
#include <cuda_fp16.h>
#include <math.h>
#include <stdint.h>

#define Bq 2
#define Lq 4096
#define Dq 1024
#define Hq 16
#define HDq 64
#define NCH 32
#define CH 128
#define BHL (Bq*Hq*Lq)

// ---- fp16 cp.async GEMM geometry (proven config) ----
#define HSTG 4
#define HBK 32
#define HASTR 40
#define HSTAGE (128*HASTR)
#define HSMEM (HSTG*2*HSTAGE*2)

// ---------------- device scratch (no allocations allowed) ----------------
__device__ __half g_xh[Bq*Lq*Dq];         // half x [8192][1024]
__device__ __half g_wh[4*Dq*Dq];          // W^T [n][k] for Wq,Wk,Wv,Wo
__device__ __half g_gwh[128*Dq];          // packed gate weights^T
__device__ __half g_omixh[Bq*Lq*Dq];
__device__ __half g_q[Bq*Hq*Lq*HDq];      // half q (silu)
__device__ __half g_k[Bq*Hq*Lq*HDq];      // half k (silu, no beta)
__device__ __half g_v[Bq*Hq*Lq*HDq];      // half v (silu, no beta)
__device__ float g_beta[BHL];
__device__ float g_fd[BHL];
__device__ float g_sd[BHL];
__device__ float g_fg[BHL];
__device__ float g_sg[BHL];
__device__ float g_psi[BHL];
__device__ float g_gf[Bq*Hq*NCH];
__device__ float g_gs[Bq*Hq*NCH];
__device__ float g_Af[Bq*Hq*NCH*HDq*HDq];
__device__ float g_As[Bq*Hq*NCH*HDq*HDq];

__device__ __forceinline__ float sigm(float x) { return 1.f / (1.f + expf(-x)); }

__device__ __forceinline__ uint32_t smem_u32(const void* p) {
    return (uint32_t)__cvta_generic_to_shared(p);
}

__device__ __forceinline__ void cp16h(__half* dst, const __half* src) {
    uint32_t d = (uint32_t)__cvta_generic_to_shared(dst);
    asm volatile("cp.async.cg.shared.global [%0], [%1], 16;" :: "r"(d), "l"(src));
}

__device__ __forceinline__ void ldsm_x4(
    uint32_t& r0, uint32_t& r1, uint32_t& r2, uint32_t& r3, uint32_t addr)
{
    asm volatile("ldmatrix.sync.aligned.m8n8.x4.shared.b16 {%0,%1,%2,%3}, [%4];"
        : "=r"(r0), "=r"(r1), "=r"(r2), "=r"(r3) : "r"(addr));
}

// fp16 k16 mma, f32 accum
__device__ __forceinline__ void mma_f16(
    float& c0, float& c1, float& c2, float& c3,
    uint32_t a0, uint32_t a1, uint32_t a2, uint32_t a3,
    uint32_t b0, uint32_t b1)
{
    asm volatile(
        "mma.sync.aligned.m16n8k16.row.col.f32.f16.f16.f32 "
        "{%0,%1,%2,%3}, {%4,%5,%6,%7}, {%8,%9}, {%0,%1,%2,%3};"
        : "+f"(c0), "+f"(c1), "+f"(c2), "+f"(c3)
        : "r"(a0), "r"(a1), "r"(a2), "r"(a3), "r"(b0), "r"(b1));
}

// ---------------- K0: fused conversions/packing (8704 blocks) ---------------
__global__ __launch_bounds__(256) void prep0_kernel(
    const float* __restrict__ x,
    const float* __restrict__ Wq, const float* __restrict__ Wk,
    const float* __restrict__ Wv, const float* __restrict__ Wo,
    const float* __restrict__ Wbm, const float* __restrict__ Wfd,
    const float* __restrict__ Wsd, const float* __restrict__ Wfg,
    const float* __restrict__ Wsg)
{
    __shared__ __half tile[32][33];
    const int bid = blockIdx.x;
    const int tid = threadIdx.x;

    if (bid < 4096) {
        size_t i = (size_t)bid * 256 + tid;
        const float4* s = (const float4*)x;
        float4 v0 = s[i * 2], v1 = s[i * 2 + 1];
        __half2 h0 = __floats2half2_rn(v0.x, v0.y);
        __half2 h1 = __floats2half2_rn(v0.z, v0.w);
        __half2 h2 = __floats2half2_rn(v1.x, v1.y);
        __half2 h3 = __floats2half2_rn(v1.z, v1.w);
        uint4 o;
        o.x = *(uint32_t*)&h0; o.y = *(uint32_t*)&h1;
        o.z = *(uint32_t*)&h2; o.w = *(uint32_t*)&h3;
        ((uint4*)g_xh)[i] = o;
    } else if (bid < 8192) {
        int idx = bid - 4096;
        int z = idx >> 10;
        int xy = idx & 1023;
        const float* W = (z == 0) ? Wq : (z == 1) ? Wk : (z == 2) ? Wv : Wo;
        __half* WT = g_wh + (size_t)z * Dq * Dq;
        int x0 = (xy & 31) * 32;
        int y0 = (xy >> 5) * 32;
        int tx = tid & 31, ty = tid >> 5;
#pragma unroll
        for (int i = 0; i < 4; i++)
            tile[ty + 8 * i][tx] = __float2half_rn(W[(size_t)(y0 + ty + 8 * i) * 1024 + x0 + tx]);
        __syncthreads();
#pragma unroll
        for (int i = 0; i < 4; i++)
            WT[(size_t)(x0 + ty + 8 * i) * 1024 + y0 + tx] = tile[tx][ty + 8 * i];
    } else {
        int idx = (bid - 8192) * 256 + tid;
        int n = idx >> 10, k = idx & 1023;
        __half val = __float2half_rn(0.f);
        if (n < 80) {
            int which = n >> 4, h = n & 15;
            const float* Wp = (which == 0) ? Wbm : (which == 1) ? Wfd
                             : (which == 2) ? Wsd : (which == 3) ? Wfg : Wsg;
            val = __float2half_rn(Wp[k * 16 + h]);
        }
        g_gwh[n * 1024 + k] = val;
    }
}

// ---------------- K1(+K2)/K7: fp16 cp.async GEMM, ldmatrix fragments --------
__global__ __launch_bounds__(256, 2) void gemm_f16_kernel(
    const __half* __restrict__ A, const __half* __restrict__ WTq,
    const __half* __restrict__ WTg,
    __half* __restrict__ H0, __half* __restrict__ H1, __half* __restrict__ H2,
    float* __restrict__ Cout,
    const float* __restrict__ fdb, const float* __restrict__ sdb,
    int phase)
{
    extern __shared__ __half smh[];
    __half* As = smh;
    __half* Bs = smh + HSTG * HSTAGE;

    const int bid = blockIdx.x;
    int mode, bm, bn, z = 0;
    const __half* WT;
    __half* H = H0;
    if (phase == 0) {
        if (bid < 1536) {
            z = bid >> 9;
            int idx = bid & 511;
            bn = (idx & 7) * 128;
            bm = (idx >> 3) * 128;
            mode = 1;
            WT = WTq + (size_t)z * Dq * Dq;
            H = (z == 0) ? H0 : (z == 1) ? H1 : H2;
        } else {
            bm = (bid - 1536) * 128;
            bn = 0;
            mode = 3;
            WT = WTg;
        }
    } else {
        bn = (bid & 7) * 128;
        bm = (bid >> 3) * 128;
        mode = 0;
        WT = WTq;
    }

    const int tid = threadIdx.x;
    const int lane = tid & 31;
    const int wid = tid >> 5;
    const int gid = lane >> 2;
    const int tig = lane & 3;
    const int warpM = (wid & 1) * 64;
    const int warpN = (wid >> 1) * 32;

    const int l_r = tid >> 2;
    const int l_c = (tid & 3) * 8;

    const int a_lrow = lane & 15;
    const int a_lcol = (lane >> 4) * 8;
    const int b_lrow = ((lane >> 4) & 1) * 8 + (lane & 7);
    const int b_lcol = ((lane >> 3) & 1) * 8;

    float acc[4][4][4];
#pragma unroll
    for (int mt = 0; mt < 4; mt++)
#pragma unroll
        for (int nt = 0; nt < 4; nt++)
#pragma unroll
            for (int c = 0; c < 4; c++) acc[mt][nt][c] = 0.f;

    const __half* Ab0 = A + (size_t)(bm + l_r) * 1024 + l_c;
    const __half* Ab1 = A + (size_t)(bm + l_r + 64) * 1024 + l_c;
    const __half* Bb0 = WT + (size_t)(bn + l_r) * 1024 + l_c;
    const __half* Bb1 = WT + (size_t)(bn + l_r + 64) * 1024 + l_c;
    __half* AsD0 = As + l_r * HASTR + l_c;
    __half* AsD1 = As + (l_r + 64) * HASTR + l_c;
    __half* BsD0 = Bs + l_r * HASTR + l_c;
    __half* BsD1 = Bs + (l_r + 64) * HASTR + l_c;

    const uint32_t AsU = smem_u32(As);
    const uint32_t BsU = smem_u32(Bs);

#pragma unroll
    for (int s = 0; s < HSTG - 1; s++) {
        int k0 = s * HBK;
        cp16h(AsD0 + s * HSTAGE, Ab0 + k0);
        cp16h(AsD1 + s * HSTAGE, Ab1 + k0);
        cp16h(BsD0 + s * HSTAGE, Bb0 + k0);
        cp16h(BsD1 + s * HSTAGE, Bb1 + k0);
        asm volatile("cp.async.commit_group;");
    }

#pragma unroll 1
    for (int t = 0; t < 32; t++) {
        asm volatile("cp.async.wait_group 2;");
        __syncthreads();

        const uint32_t AscU = AsU + (uint32_t)((t & 3) * HSTAGE) * 2u;
        const uint32_t BscU = BsU + (uint32_t)((t & 3) * HSTAGE) * 2u;

        uint32_t af[4][4];
        uint32_t br[2][4];
#pragma unroll
        for (int mt = 0; mt < 4; mt++) {
            uint32_t addr = AscU +
                (uint32_t)((warpM + mt * 16 + a_lrow) * HASTR + a_lcol) * 2u;
            ldsm_x4(af[mt][0], af[mt][1], af[mt][2], af[mt][3], addr);
        }
#pragma unroll
        for (int np = 0; np < 2; np++) {
            uint32_t addr = BscU +
                (uint32_t)((warpN + np * 16 + b_lrow) * HASTR + b_lcol) * 2u;
            ldsm_x4(br[np][0], br[np][1], br[np][2], br[np][3], addr);
        }

        if (t + 3 < 32) {
            int s = (t + 3) & 3;
            int k0 = (t + 3) * HBK;
            cp16h(AsD0 + s * HSTAGE, Ab0 + k0);
            cp16h(AsD1 + s * HSTAGE, Ab1 + k0);
            cp16h(BsD0 + s * HSTAGE, Bb0 + k0);
            cp16h(BsD1 + s * HSTAGE, Bb1 + k0);
        }
        asm volatile("cp.async.commit_group;");

#pragma unroll
        for (int nt = 0; nt < 4; nt++) {
            uint32_t b0 = br[nt >> 1][(nt & 1) * 2 + 0];
            uint32_t b1 = br[nt >> 1][(nt & 1) * 2 + 1];
#pragma unroll
            for (int mt = 0; mt < 4; mt++) {
                mma_f16(acc[mt][nt][0], acc[mt][nt][1], acc[mt][nt][2], acc[mt][nt][3],
                        af[mt][0], af[mt][1], af[mt][2], af[mt][3], b0, b1);
            }
        }

#pragma unroll
        for (int mt = 0; mt < 4; mt++) {
            uint32_t addr = AscU +
                (uint32_t)((warpM + mt * 16 + a_lrow) * HASTR + 16 + a_lcol) * 2u;
            ldsm_x4(af[mt][0], af[mt][1], af[mt][2], af[mt][3], addr);
        }
#pragma unroll
        for (int np = 0; np < 2; np++) {
            uint32_t addr = BscU +
                (uint32_t)((warpN + np * 16 + b_lrow) * HASTR + 16 + b_lcol) * 2u;
            ldsm_x4(br[np][0], br[np][1], br[np][2], br[np][3], addr);
        }
#pragma unroll
        for (int nt = 0; nt < 4; nt++) {
            uint32_t b0 = br[nt >> 1][(nt & 1) * 2 + 0];
            uint32_t b1 = br[nt >> 1][(nt & 1) * 2 + 1];
#pragma unroll
            for (int mt = 0; mt < 4; mt++) {
                mma_f16(acc[mt][nt][0], acc[mt][nt][1], acc[mt][nt][2], acc[mt][nt][3],
                        af[mt][0], af[mt][1], af[mt][2], af[mt][3], b0, b1);
            }
        }
    }

    // epilogue
#pragma unroll
    for (int mt = 0; mt < 4; mt++) {
#pragma unroll
        for (int nt = 0; nt < 4; nt++) {
            int row = bm + warpM + mt * 16 + gid;
            int col = bn + warpN + nt * 8 + tig * 2;
#pragma unroll
            for (int half_ = 0; half_ < 2; half_++) {
                int r = row + half_ * 8;
                float v0 = acc[mt][nt][half_ * 2 + 0];
                float v1 = acc[mt][nt][half_ * 2 + 1];
                int bb = r >> 12, l = r & 4095;
                if (mode == 1) {
                    v0 = v0 * (1.f / (1.f + expf(-v0)));
                    v1 = v1 * (1.f / (1.f + expf(-v1)));
                    int h = col >> 6, hd = col & 63;
                    __half2 hv = __floats2half2_rn(v0, v1);
                    *(__half2*)(H + (((size_t)(bb * Hq + h) * Lq + l) * HDq) + hd) = hv;
                } else if (mode == 3) {
#pragma unroll
                    for (int cc = 0; cc < 2; cc++) {
                        int cl = col + cc;
                        if (cl < 80) {
                            int which = cl >> 4, h = cl & 15;
                            float s = (cc == 0) ? v0 : v1;
                            if (which == 1) s += fdb[h];
                            if (which == 2) s += sdb[h];
                            float val = sigm(s);
                            float* dst = (which == 0) ? g_beta : (which == 1) ? g_fd
                                        : (which == 2) ? g_sd : (which == 3) ? g_fg : g_sg;
                            dst[(bb * Hq + h) * Lq + l] = val;
                        }
                    }
                } else {
                    *(float2*)(Cout + (size_t)r * 1024 + col) = make_float2(v0, v1);
                }
            }
        }
    }
}

// ---------------- K4: outer products + psi/surprise + chunk decay (fused) ---
__global__ __launch_bounds__(256) void outer_kernel()
{
    __shared__ float Ks[64 * 64];
    __shared__ float Vs[64 * 64];
    __shared__ float S2[64];
    __shared__ float fdm_s[128];
    __shared__ float sdm_s[128];
    const int bhn = blockIdx.x;
    const int bh = bhn / NCH, n = bhn % NCH;
    const int t = threadIdx.x;
    const int d0 = (t & 15) * 4;
    const int e0 = (t >> 4) * 4;
    const int posbase = bh * Lq + n * CH;

    float af[4][4], as_[4][4];
#pragma unroll
    for (int i = 0; i < 4; i++)
#pragma unroll
        for (int j = 0; j < 4; j++) { af[i][j] = 0.f; as_[i][j] = 0.f; }

    for (int half_ = 0; half_ < 2; half_++) {
        size_t base = ((size_t)(posbase + half_ * 64)) * HDq;
        for (int i = t; i < 512; i += 256) {
            int row = i >> 3;
            float b = g_beta[posbase + half_ * 64 + row];
            uint4 kr = ((const uint4*)(g_k + base))[i];
            uint4 vr = ((const uint4*)(g_v + base))[i];
            float* kd = &Ks[i * 8];
            float* vd = &Vs[i * 8];
            const __half2* kh = (const __half2*)&kr;
            const __half2* vh = (const __half2*)&vr;
#pragma unroll
            for (int j = 0; j < 4; j++) {
                float2 kf = __half22float2(kh[j]);
                float2 vf = __half22float2(vh[j]);
                kd[j * 2 + 0] = kf.x * b; kd[j * 2 + 1] = kf.y * b;
                vd[j * 2 + 0] = vf.x * b; vd[j * 2 + 1] = vf.y * b;
            }
        }
        __syncthreads();

        {
            int r = t >> 2, q = t & 3;
            const float4* krow = (const float4*)&Ks[r * 64 + q * 16];
            const float4* vrow = (const float4*)&Vs[r * 64 + q * 16];
            float kk = 0.f, vv = 0.f, kv = 0.f;
#pragma unroll
            for (int j = 0; j < 4; j++) {
                float4 a = krow[j], b = vrow[j];
                kk += a.x * a.x + a.y * a.y + a.z * a.z + a.w * a.w;
                vv += b.x * b.x + b.y * b.y + b.z * b.z + b.w * b.w;
                kv += a.x * b.x + a.y * b.y + a.z * b.z + a.w * b.w;
            }
            kk += __shfl_xor_sync(0xffffffffu, kk, 1);
            kk += __shfl_xor_sync(0xffffffffu, kk, 2);
            vv += __shfl_xor_sync(0xffffffffu, vv, 1);
            vv += __shfl_xor_sync(0xffffffffu, vv, 2);
            kv += __shfl_xor_sync(0xffffffffu, kv, 1);
            kv += __shfl_xor_sync(0xffffffffu, kv, 2);
            if (q == 0) {
                float kn = sqrtf(kk) + 1e-8f;
                float vn = sqrtf(vv) + 1e-8f;
                float praw = fabsf(kv) / (kn * vn);
                float psi = sigm(3.f * praw);
                float sur = sigm((psi - 0.5f) * 10.f);
                S2[r] = sur * sur;
                int p = posbase + half_ * 64 + r;
                g_psi[p] = psi;
                fdm_s[half_ * 64 + r] = g_fd[p] * (1.f - 0.1f * psi);
                sdm_s[half_ * 64 + r] = g_sd[p] * (1.f - 0.05f * psi);
            }
        }
        __syncthreads();

#pragma unroll 4
        for (int l = 0; l < 64; l++) {
            float4 vv4 = *(float4*)&Vs[l * 64 + d0];
            float4 kk4 = *(float4*)&Ks[l * 64 + e0];
            float s2 = S2[l];
            float v[4] = {vv4.x, vv4.y, vv4.z, vv4.w};
            float k[4] = {kk4.x, kk4.y, kk4.z, kk4.w};
            float vs[4] = {v[0] * s2, v[1] * s2, v[2] * s2, v[3] * s2};
#pragma unroll
            for (int i = 0; i < 4; i++)
#pragma unroll
                for (int j = 0; j < 4; j++) {
                    af[i][j] += v[i] * k[j];
                    as_[i][j] += vs[i] * k[j];
                }
        }
        __syncthreads();
    }

    if (t < 32) {
        float f = 0.f, s = 0.f;
#pragma unroll
        for (int j = t; j < 128; j += 32) { f += fdm_s[j]; s += sdm_s[j]; }
#pragma unroll
        for (int off = 16; off; off >>= 1) {
            f += __shfl_xor_sync(0xffffffffu, f, off);
            s += __shfl_xor_sync(0xffffffffu, s, off);
        }
        if (t == 0) {
            float gf = f * (1.f / 128.f), gs = s * (1.f / 128.f);
#pragma unroll
            for (int i = 0; i < 7; i++) { gf *= gf; gs *= gs; }
            g_gf[bhn] = gf;
            g_gs[bhn] = gs;
        }
    }

    size_t abase = (size_t)bhn * 4096;
#pragma unroll
    for (int i = 0; i < 4; i++) {
        *(float4*)&g_Af[abase + (d0 + i) * 64 + e0] =
            make_float4(af[i][0], af[i][1], af[i][2], af[i][3]);
        *(float4*)&g_As[abase + (d0 + i) * 64 + e0] =
            make_float4(as_[i][0], as_[i][1], as_[i][2], as_[i][3]);
    }
}

// ---------------- K5: decayed prefix scan — batched MLP, float2 -------------
// 256 blocks: bh = blockIdx.x>>3, eb = blockIdx.x&7; each thread 2 entries.
__global__ __launch_bounds__(256) void scan_kernel()
{
    const int bh = blockIdx.x >> 3;
    const int eb = blockIdx.x & 7;
    const int e2 = eb * 256 + threadIdx.x;       // float2 index 0..2047
    float2* Af2 = (float2*)g_Af;
    float2* As2 = (float2*)g_As;
    const size_t idx2 = (size_t)bh * NCH * 2048 + e2;

    float2 sf = make_float2(0.f, 0.f);
    float2 ss = make_float2(0.f, 0.f);

#pragma unroll 1
    for (int n0 = 0; n0 < NCH; n0 += 8) {
        float2 a[8], b[8];
        float gf[8], gs[8];
#pragma unroll
        for (int j = 0; j < 8; j++) {
            int bhn = bh * NCH + n0 + j;
            gf[j] = g_gf[bhn];
            gs[j] = g_gs[bhn];
            a[j] = Af2[idx2 + (size_t)(n0 + j) * 2048];
            b[j] = As2[idx2 + (size_t)(n0 + j) * 2048];
        }
#pragma unroll
        for (int j = 0; j < 8; j++) {
            sf.x = sf.x * gf[j] + a[j].x;
            sf.y = sf.y * gf[j] + a[j].y;
            ss.x = ss.x * gs[j] + b[j].x;
            ss.y = ss.y * gs[j] + b[j].y;
            a[j] = sf;
            b[j] = ss;
        }
#pragma unroll
        for (int j = 0; j < 8; j++) {
            Af2[idx2 + (size_t)(n0 + j) * 2048] = a[j];
            As2[idx2 + (size_t)(n0 + j) * 2048] = b[j];
        }
    }
}

// ---------------- K6: O = Q @ S (fast+slow), gate/alpha mix -> omix (half) --
__global__ __launch_bounds__(256) void outmix_kernel()
{
    __shared__ float Sf[4096];
    __shared__ float Ss[4096];
    __shared__ float Qs[32 * 64];
    __shared__ float gA[32], gB[32];
    const int bhn = blockIdx.x;
    const int bh = bhn / NCH, n = bhn % NCH;
    const int b = bh >> 4, h = bh & 15;
    const int t = threadIdx.x;

    size_t abase = (size_t)bhn * 4096;
    for (int i = t; i < 1024; i += 256) {
        ((float4*)Sf)[i] = ((const float4*)(g_Af + abase))[i];
        ((float4*)Ss)[i] = ((const float4*)(g_As + abase))[i];
    }

    const int d = t & 63;
    const int lb = (t >> 6) * 8;

    for (int pass = 0; pass < 4; pass++) {
        int l0 = pass * 32;
        size_t qbase = ((size_t)bh * Lq + n * CH + l0) * HDq;
        for (int i = t; i < 256; i += 256) {
            uint4 qr = ((const uint4*)(g_q + qbase))[i];
            const __half2* qh = (const __half2*)&qr;
            float* qd = &Qs[i * 8];
#pragma unroll
            for (int j = 0; j < 4; j++) {
                float2 qf = __half22float2(qh[j]);
                qd[j * 2 + 0] = qf.x;
                qd[j * 2 + 1] = qf.y;
            }
        }
        if (t < 32) {
            int p = bh * Lq + n * CH + l0 + t;
            float psi = g_psi[p];
            float alpha = 0.5f + 0.3f * psi;
            gA[t] = alpha * g_fg[p];
            gB[t] = (1.f - alpha) * g_sg[p];
        }
        __syncthreads();

        float accf[8], accs[8];
#pragma unroll
        for (int l = 0; l < 8; l++) { accf[l] = 0.f; accs[l] = 0.f; }
#pragma unroll 8
        for (int e = 0; e < 64; e += 2) {
            float sf0 = Sf[e * 64 + d];
            float sf1 = Sf[(e + 1) * 64 + d];
            float ss0 = Ss[e * 64 + d];
            float ss1 = Ss[(e + 1) * 64 + d];
#pragma unroll
            for (int l = 0; l < 8; l++) {
                float2 q2 = *(float2*)&Qs[(lb + l) * 64 + e];
                accf[l] += q2.x * sf0 + q2.y * sf1;
                accs[l] += q2.x * ss0 + q2.y * ss1;
            }
        }
#pragma unroll
        for (int l = 0; l < 8; l++) {
            int ll = lb + l;
            float val = gA[ll] * accf[l] + gB[ll] * accs[l];
            int lglob = n * CH + l0 + ll;
            g_omixh[((size_t)b * Lq + lglob) * Dq + h * HDq + d] = __float2half_rn(val);
        }
        __syncthreads();
    }
}

// ---------------- launch ----------------
extern "C" void kernel_launch(void* const* d_in, const int* in_sizes, int n_in,
                              void* d_out, int out_size)
{
    const float* x   = (const float*)d_in[0];
    const float* Wq  = (const float*)d_in[1];
    const float* Wk  = (const float*)d_in[2];
    const float* Wv  = (const float*)d_in[3];
    const float* Wb  = (const float*)d_in[4];
    const float* Wfd = (const float*)d_in[5];
    const float* fdb = (const float*)d_in[6];
    const float* Wsd = (const float*)d_in[7];
    const float* sdb = (const float*)d_in[8];
    const float* Wfg = (const float*)d_in[9];
    const float* Wsg = (const float*)d_in[10];
    const float* Wo  = (const float*)d_in[11];
    float* out = (float*)d_out;

    void *p_q = nullptr, *p_k = nullptr, *p_v = nullptr;
    void *p_xh = nullptr, *p_wh = nullptr, *p_gwh = nullptr, *p_oh = nullptr;
    cudaGetSymbolAddress(&p_q, g_q);
    cudaGetSymbolAddress(&p_k, g_k);
    cudaGetSymbolAddress(&p_v, g_v);
    cudaGetSymbolAddress(&p_xh, g_xh);
    cudaGetSymbolAddress(&p_wh, g_wh);
    cudaGetSymbolAddress(&p_gwh, g_gwh);
    cudaGetSymbolAddress(&p_oh, g_omixh);

    cudaFuncSetAttribute(gemm_f16_kernel,
                         cudaFuncAttributeMaxDynamicSharedMemorySize, HSMEM);

    // K0: fused conversions & packing
    prep0_kernel<<<8704, 256>>>(x, Wq, Wk, Wv, Wo, Wb, Wfd, Wsd, Wfg, Wsg);

    // K1+K2: fused QKV + gate projections (1600 blocks), half q/k/v out
    gemm_f16_kernel<<<1600, 256, HSMEM>>>(
        (const __half*)p_xh, (const __half*)p_wh, (const __half*)p_gwh,
        (__half*)p_q, (__half*)p_k, (__half*)p_v, nullptr, fdb, sdb, 0);

    // K4: fused outer products + psi/surprise + chunk decay
    outer_kernel<<<Bq * Hq * NCH, 256>>>();

    // K5: decayed scan (batched MLP)
    scan_kernel<<<256, 256>>>();

    // K6: per-chunk output + gate mixing (half omix)
    outmix_kernel<<<Bq * Hq * NCH, 256>>>();

    // K7: output projection (512 blocks, fp32 out)
    gemm_f16_kernel<<<512, 256, HSMEM>>>(
        (const __half*)p_oh, (const __half*)p_wh + (size_t)3 * Dq * Dq,
        (const __half*)p_gwh, nullptr, nullptr, nullptr, out, fdb, sdb, 1);
}

// round 15
// speedup vs baseline: 1.9388x; 1.3019x over previous
#include <cuda_runtime.h>
#include <cuda_fp16.h>
#include <math.h>
#include <stdint.h>

#define Bq 2
#define Lq 4096
#define Dq 1024
#define Hq 16
#define HDq 64
#define NCH 32
#define CH 128
#define BHL (Bq*Hq*Lq)

// ---- fp16 cp.async GEMM geometry (proven config) ----
#define HSTG 4
#define HBK 32
#define HASTR 40
#define HSTAGE (128*HASTR)
#define HSMEM (HSTG*2*HSTAGE*2)

// ---- recurrence mma tile stride (halves) ----
#define ESTR 72
#define OUTER_SMEM (3*128*ESTR*2)     // Kh, Vh, Vsh = 55296 B

// ---------------- device scratch (no allocations allowed) ----------------
__device__ __half g_xh[Bq*Lq*Dq];
__device__ __half g_wh[4*Dq*Dq];
__device__ __half g_gwh[128*Dq];
__device__ __half g_omixh[Bq*Lq*Dq];
__device__ __half g_q[Bq*Hq*Lq*HDq];
__device__ __half g_k[Bq*Hq*Lq*HDq];
__device__ __half g_v[Bq*Hq*Lq*HDq];
__device__ float g_beta[BHL];
__device__ float g_fd[BHL];
__device__ float g_sd[BHL];
__device__ float g_fg[BHL];
__device__ float g_sg[BHL];
__device__ float g_psi[BHL];
__device__ float g_gf[Bq*Hq*NCH];
__device__ float g_gs[Bq*Hq*NCH];
__device__ float g_Af[Bq*Hq*NCH*HDq*HDq];
__device__ float g_As[Bq*Hq*NCH*HDq*HDq];

__device__ __forceinline__ float sigm(float x) { return 1.f / (1.f + expf(-x)); }

__device__ __forceinline__ uint32_t smem_u32(const void* p) {
    return (uint32_t)__cvta_generic_to_shared(p);
}

__device__ __forceinline__ void cp16h(__half* dst, const __half* src) {
    uint32_t d = (uint32_t)__cvta_generic_to_shared(dst);
    asm volatile("cp.async.cg.shared.global [%0], [%1], 16;" :: "r"(d), "l"(src));
}

__device__ __forceinline__ void ldsm_x4(
    uint32_t& r0, uint32_t& r1, uint32_t& r2, uint32_t& r3, uint32_t addr)
{
    asm volatile("ldmatrix.sync.aligned.m8n8.x4.shared.b16 {%0,%1,%2,%3}, [%4];"
        : "=r"(r0), "=r"(r1), "=r"(r2), "=r"(r3) : "r"(addr));
}

__device__ __forceinline__ void ldsm_x4_t(
    uint32_t& r0, uint32_t& r1, uint32_t& r2, uint32_t& r3, uint32_t addr)
{
    asm volatile("ldmatrix.sync.aligned.m8n8.x4.trans.shared.b16 {%0,%1,%2,%3}, [%4];"
        : "=r"(r0), "=r"(r1), "=r"(r2), "=r"(r3) : "r"(addr));
}

// fp16 k16 mma, f32 accum
__device__ __forceinline__ void mma_f16(
    float& c0, float& c1, float& c2, float& c3,
    uint32_t a0, uint32_t a1, uint32_t a2, uint32_t a3,
    uint32_t b0, uint32_t b1)
{
    asm volatile(
        "mma.sync.aligned.m16n8k16.row.col.f32.f16.f16.f32 "
        "{%0,%1,%2,%3}, {%4,%5,%6,%7}, {%8,%9}, {%0,%1,%2,%3};"
        : "+f"(c0), "+f"(c1), "+f"(c2), "+f"(c3)
        : "r"(a0), "r"(a1), "r"(a2), "r"(a3), "r"(b0), "r"(b1));
}

// ---------------- K0: fused conversions/packing (8704 blocks) ---------------
__global__ __launch_bounds__(256) void prep0_kernel(
    const float* __restrict__ x,
    const float* __restrict__ Wq, const float* __restrict__ Wk,
    const float* __restrict__ Wv, const float* __restrict__ Wo,
    const float* __restrict__ Wbm, const float* __restrict__ Wfd,
    const float* __restrict__ Wsd, const float* __restrict__ Wfg,
    const float* __restrict__ Wsg)
{
    __shared__ __half tile[32][33];
    const int bid = blockIdx.x;
    const int tid = threadIdx.x;

    if (bid < 4096) {
        size_t i = (size_t)bid * 256 + tid;
        const float4* s = (const float4*)x;
        float4 v0 = s[i * 2], v1 = s[i * 2 + 1];
        __half2 h0 = __floats2half2_rn(v0.x, v0.y);
        __half2 h1 = __floats2half2_rn(v0.z, v0.w);
        __half2 h2 = __floats2half2_rn(v1.x, v1.y);
        __half2 h3 = __floats2half2_rn(v1.z, v1.w);
        uint4 o;
        o.x = *(uint32_t*)&h0; o.y = *(uint32_t*)&h1;
        o.z = *(uint32_t*)&h2; o.w = *(uint32_t*)&h3;
        ((uint4*)g_xh)[i] = o;
    } else if (bid < 8192) {
        int idx = bid - 4096;
        int z = idx >> 10;
        int xy = idx & 1023;
        const float* W = (z == 0) ? Wq : (z == 1) ? Wk : (z == 2) ? Wv : Wo;
        __half* WT = g_wh + (size_t)z * Dq * Dq;
        int x0 = (xy & 31) * 32;
        int y0 = (xy >> 5) * 32;
        int tx = tid & 31, ty = tid >> 5;
#pragma unroll
        for (int i = 0; i < 4; i++)
            tile[ty + 8 * i][tx] = __float2half_rn(W[(size_t)(y0 + ty + 8 * i) * 1024 + x0 + tx]);
        __syncthreads();
#pragma unroll
        for (int i = 0; i < 4; i++)
            WT[(size_t)(x0 + ty + 8 * i) * 1024 + y0 + tx] = tile[tx][ty + 8 * i];
    } else {
        int idx = (bid - 8192) * 256 + tid;
        int n = idx >> 10, k = idx & 1023;
        __half val = __float2half_rn(0.f);
        if (n < 80) {
            int which = n >> 4, h = n & 15;
            const float* Wp = (which == 0) ? Wbm : (which == 1) ? Wfd
                             : (which == 2) ? Wsd : (which == 3) ? Wfg : Wsg;
            val = __float2half_rn(Wp[k * 16 + h]);
        }
        g_gwh[n * 1024 + k] = val;
    }
}

// ---------------- K1(+K2)/K7: fp16 cp.async GEMM, ldmatrix fragments --------
__global__ __launch_bounds__(256, 2) void gemm_f16_kernel(
    const __half* __restrict__ A, const __half* __restrict__ WTq,
    const __half* __restrict__ WTg,
    __half* __restrict__ H0, __half* __restrict__ H1, __half* __restrict__ H2,
    float* __restrict__ Cout,
    const float* __restrict__ fdb, const float* __restrict__ sdb,
    int phase)
{
    extern __shared__ __half smh[];
    __half* As = smh;
    __half* Bs = smh + HSTG * HSTAGE;

    const int bid = blockIdx.x;
    int mode, bm, bn, z = 0;
    const __half* WT;
    __half* H = H0;
    if (phase == 0) {
        if (bid < 1536) {
            z = bid >> 9;
            int idx = bid & 511;
            bn = (idx & 7) * 128;
            bm = (idx >> 3) * 128;
            mode = 1;
            WT = WTq + (size_t)z * Dq * Dq;
            H = (z == 0) ? H0 : (z == 1) ? H1 : H2;
        } else {
            bm = (bid - 1536) * 128;
            bn = 0;
            mode = 3;
            WT = WTg;
        }
    } else {
        bn = (bid & 7) * 128;
        bm = (bid >> 3) * 128;
        mode = 0;
        WT = WTq;
    }

    const int tid = threadIdx.x;
    const int lane = tid & 31;
    const int wid = tid >> 5;
    const int gid = lane >> 2;
    const int tig = lane & 3;
    const int warpM = (wid & 1) * 64;
    const int warpN = (wid >> 1) * 32;

    const int l_r = tid >> 2;
    const int l_c = (tid & 3) * 8;

    const int a_lrow = lane & 15;
    const int a_lcol = (lane >> 4) * 8;
    const int b_lrow = ((lane >> 4) & 1) * 8 + (lane & 7);
    const int b_lcol = ((lane >> 3) & 1) * 8;

    float acc[4][4][4];
#pragma unroll
    for (int mt = 0; mt < 4; mt++)
#pragma unroll
        for (int nt = 0; nt < 4; nt++)
#pragma unroll
            for (int c = 0; c < 4; c++) acc[mt][nt][c] = 0.f;

    const __half* Ab0 = A + (size_t)(bm + l_r) * 1024 + l_c;
    const __half* Ab1 = A + (size_t)(bm + l_r + 64) * 1024 + l_c;
    const __half* Bb0 = WT + (size_t)(bn + l_r) * 1024 + l_c;
    const __half* Bb1 = WT + (size_t)(bn + l_r + 64) * 1024 + l_c;
    __half* AsD0 = As + l_r * HASTR + l_c;
    __half* AsD1 = As + (l_r + 64) * HASTR + l_c;
    __half* BsD0 = Bs + l_r * HASTR + l_c;
    __half* BsD1 = Bs + (l_r + 64) * HASTR + l_c;

    const uint32_t AsU = smem_u32(As);
    const uint32_t BsU = smem_u32(Bs);

#pragma unroll
    for (int s = 0; s < HSTG - 1; s++) {
        int k0 = s * HBK;
        cp16h(AsD0 + s * HSTAGE, Ab0 + k0);
        cp16h(AsD1 + s * HSTAGE, Ab1 + k0);
        cp16h(BsD0 + s * HSTAGE, Bb0 + k0);
        cp16h(BsD1 + s * HSTAGE, Bb1 + k0);
        asm volatile("cp.async.commit_group;");
    }

#pragma unroll 1
    for (int t = 0; t < 32; t++) {
        asm volatile("cp.async.wait_group 2;");
        __syncthreads();

        const uint32_t AscU = AsU + (uint32_t)((t & 3) * HSTAGE) * 2u;
        const uint32_t BscU = BsU + (uint32_t)((t & 3) * HSTAGE) * 2u;

        uint32_t af[4][4];
        uint32_t br[2][4];
#pragma unroll
        for (int mt = 0; mt < 4; mt++) {
            uint32_t addr = AscU +
                (uint32_t)((warpM + mt * 16 + a_lrow) * HASTR + a_lcol) * 2u;
            ldsm_x4(af[mt][0], af[mt][1], af[mt][2], af[mt][3], addr);
        }
#pragma unroll
        for (int np = 0; np < 2; np++) {
            uint32_t addr = BscU +
                (uint32_t)((warpN + np * 16 + b_lrow) * HASTR + b_lcol) * 2u;
            ldsm_x4(br[np][0], br[np][1], br[np][2], br[np][3], addr);
        }

        if (t + 3 < 32) {
            int s = (t + 3) & 3;
            int k0 = (t + 3) * HBK;
            cp16h(AsD0 + s * HSTAGE, Ab0 + k0);
            cp16h(AsD1 + s * HSTAGE, Ab1 + k0);
            cp16h(BsD0 + s * HSTAGE, Bb0 + k0);
            cp16h(BsD1 + s * HSTAGE, Bb1 + k0);
        }
        asm volatile("cp.async.commit_group;");

#pragma unroll
        for (int nt = 0; nt < 4; nt++) {
            uint32_t b0 = br[nt >> 1][(nt & 1) * 2 + 0];
            uint32_t b1 = br[nt >> 1][(nt & 1) * 2 + 1];
#pragma unroll
            for (int mt = 0; mt < 4; mt++) {
                mma_f16(acc[mt][nt][0], acc[mt][nt][1], acc[mt][nt][2], acc[mt][nt][3],
                        af[mt][0], af[mt][1], af[mt][2], af[mt][3], b0, b1);
            }
        }

#pragma unroll
        for (int mt = 0; mt < 4; mt++) {
            uint32_t addr = AscU +
                (uint32_t)((warpM + mt * 16 + a_lrow) * HASTR + 16 + a_lcol) * 2u;
            ldsm_x4(af[mt][0], af[mt][1], af[mt][2], af[mt][3], addr);
        }
#pragma unroll
        for (int np = 0; np < 2; np++) {
            uint32_t addr = BscU +
                (uint32_t)((warpN + np * 16 + b_lrow) * HASTR + 16 + b_lcol) * 2u;
            ldsm_x4(br[np][0], br[np][1], br[np][2], br[np][3], addr);
        }
#pragma unroll
        for (int nt = 0; nt < 4; nt++) {
            uint32_t b0 = br[nt >> 1][(nt & 1) * 2 + 0];
            uint32_t b1 = br[nt >> 1][(nt & 1) * 2 + 1];
#pragma unroll
            for (int mt = 0; mt < 4; mt++) {
                mma_f16(acc[mt][nt][0], acc[mt][nt][1], acc[mt][nt][2], acc[mt][nt][3],
                        af[mt][0], af[mt][1], af[mt][2], af[mt][3], b0, b1);
            }
        }
    }

    // epilogue
#pragma unroll
    for (int mt = 0; mt < 4; mt++) {
#pragma unroll
        for (int nt = 0; nt < 4; nt++) {
            int row = bm + warpM + mt * 16 + gid;
            int col = bn + warpN + nt * 8 + tig * 2;
#pragma unroll
            for (int half_ = 0; half_ < 2; half_++) {
                int r = row + half_ * 8;
                float v0 = acc[mt][nt][half_ * 2 + 0];
                float v1 = acc[mt][nt][half_ * 2 + 1];
                int bb = r >> 12, l = r & 4095;
                if (mode == 1) {
                    v0 = v0 * (1.f / (1.f + expf(-v0)));
                    v1 = v1 * (1.f / (1.f + expf(-v1)));
                    int h = col >> 6, hd = col & 63;
                    __half2 hv = __floats2half2_rn(v0, v1);
                    *(__half2*)(H + (((size_t)(bb * Hq + h) * Lq + l) * HDq) + hd) = hv;
                } else if (mode == 3) {
#pragma unroll
                    for (int cc = 0; cc < 2; cc++) {
                        int cl = col + cc;
                        if (cl < 80) {
                            int which = cl >> 4, h = cl & 15;
                            float s = (cc == 0) ? v0 : v1;
                            if (which == 1) s += fdb[h];
                            if (which == 2) s += sdb[h];
                            float val = sigm(s);
                            float* dst = (which == 0) ? g_beta : (which == 1) ? g_fd
                                        : (which == 2) ? g_sd : (which == 3) ? g_fg : g_sg;
                            dst[(bb * Hq + h) * Lq + l] = val;
                        }
                    }
                } else {
                    *(float2*)(Cout + (size_t)r * 1024 + col) = make_float2(v0, v1);
                }
            }
        }
    }
}

// ---------------- K4: outer products via fp16 mma (+psi+chunk decay) --------
__global__ __launch_bounds__(256) void outer_kernel()
{
    extern __shared__ __half osm[];
    __half* Kh  = osm;                       // [128][ESTR]
    __half* Vh  = osm + 128 * ESTR;
    __half* Vsh = osm + 2 * 128 * ESTR;
    __shared__ float S2f[128];
    __shared__ float fdm_s[128];
    __shared__ float sdm_s[128];

    const int bhn = blockIdx.x;
    const int bh = bhn / NCH, n = bhn % NCH;
    const int t = threadIdx.x;
    const int lane = t & 31;
    const int wid = t >> 5;
    const int gid = lane >> 2;
    const int tig = lane & 3;
    const int posbase = bh * Lq + n * CH;
    const size_t kvbase8 = (size_t)posbase * 8;    // uint4 index into g_k/g_v

    // fill Kh, Vh with beta-scaled halves
    for (int i = t; i < 1024; i += 256) {
        int row = i >> 3;
        int c8 = (i & 7) * 8;
        float b = g_beta[posbase + row];
        uint4 kr = ((const uint4*)g_k)[kvbase8 + i];
        uint4 vr = ((const uint4*)g_v)[kvbase8 + i];
        const __half2* kh = (const __half2*)&kr;
        const __half2* vh = (const __half2*)&vr;
        uint4 ko, vo;
        __half2* kop = (__half2*)&ko;
        __half2* vop = (__half2*)&vo;
#pragma unroll
        for (int j = 0; j < 4; j++) {
            float2 kf = __half22float2(kh[j]);
            float2 vf = __half22float2(vh[j]);
            kop[j] = __floats2half2_rn(kf.x * b, kf.y * b);
            vop[j] = __floats2half2_rn(vf.x * b, vf.y * b);
        }
        *(uint4*)&Kh[row * ESTR + c8] = ko;
        *(uint4*)&Vh[row * ESTR + c8] = vo;
    }
    __syncthreads();

    // psi per row (2 threads/row)
    {
        int r = t >> 1, q = t & 1;
        const __half2* kp = (const __half2*)&Kh[r * ESTR + q * 32];
        const __half2* vp = (const __half2*)&Vh[r * ESTR + q * 32];
        float kk = 0.f, vv = 0.f, kv = 0.f;
#pragma unroll
        for (int j = 0; j < 16; j++) {
            float2 a = __half22float2(kp[j]);
            float2 b = __half22float2(vp[j]);
            kk += a.x * a.x + a.y * a.y;
            vv += b.x * b.x + b.y * b.y;
            kv += a.x * b.x + a.y * b.y;
        }
        kk += __shfl_xor_sync(0xffffffffu, kk, 1);
        vv += __shfl_xor_sync(0xffffffffu, vv, 1);
        kv += __shfl_xor_sync(0xffffffffu, kv, 1);
        if (q == 0) {
            float kn = sqrtf(kk) + 1e-8f;
            float vn = sqrtf(vv) + 1e-8f;
            float praw = fabsf(kv) / (kn * vn);
            float psi = sigm(3.f * praw);
            float sur = sigm((psi - 0.5f) * 10.f);
            S2f[r] = sur * sur;
            int p = posbase + r;
            g_psi[p] = psi;
            fdm_s[r] = g_fd[p] * (1.f - 0.1f * psi);
            sdm_s[r] = g_sd[p] * (1.f - 0.05f * psi);
        }
    }
    __syncthreads();

    // fill Vsh = Vh * s2
    for (int i = t; i < 1024; i += 256) {
        int row = i >> 3;
        int c8 = (i & 7) * 8;
        float s2 = S2f[row];
        uint4 vr = *(const uint4*)&Vh[row * ESTR + c8];
        const __half2* vh = (const __half2*)&vr;
        uint4 vo;
        __half2* vop = (__half2*)&vo;
#pragma unroll
        for (int j = 0; j < 4; j++) {
            float2 vf = __half22float2(vh[j]);
            vop[j] = __floats2half2_rn(vf.x * s2, vf.y * s2);
        }
        *(uint4*)&Vsh[row * ESTR + c8] = vo;
    }
    __syncthreads();

    // mma: C[d,e] = sum_l A[d,l]*K[l,e]; A = (Vh or Vsh)^T via trans-ldmatrix
    {
        const bool slow = (wid >= 4);
        const int wm = (wid & 3) * 16;                 // d tile
        const uint32_t AU = smem_u32(slow ? Vsh : Vh);
        const uint32_t KU = smem_u32(Kh);
        float* dst = (slow ? g_As : g_Af) + (size_t)bhn * 4096;

        const int arow_t = (lane & 7) + ((lane >> 4) & 1) * 8;
        const int acol_t = ((lane >> 3) & 1) * 8;
        const int brow_t = (lane & 7) + ((lane >> 3) & 1) * 8;
        const int bcol_t = ((lane >> 4) & 1) * 8;

        float acc[8][4];
#pragma unroll
        for (int nt = 0; nt < 8; nt++)
#pragma unroll
            for (int c = 0; c < 4; c++) acc[nt][c] = 0.f;

#pragma unroll
        for (int kc = 0; kc < 8; kc++) {
            int l0 = kc * 16;
            uint32_t a0, a1, a2, a3;
            ldsm_x4_t(a0, a1, a2, a3,
                AU + (uint32_t)((l0 + arow_t) * ESTR + wm + acol_t) * 2u);
#pragma unroll
            for (int et = 0; et < 4; et++) {
                int e0 = et * 16;
                uint32_t b0, b1, b2, b3;
                ldsm_x4_t(b0, b1, b2, b3,
                    KU + (uint32_t)((l0 + brow_t) * ESTR + e0 + bcol_t) * 2u);
                mma_f16(acc[et*2][0], acc[et*2][1], acc[et*2][2], acc[et*2][3],
                        a0, a1, a2, a3, b0, b1);
                mma_f16(acc[et*2+1][0], acc[et*2+1][1], acc[et*2+1][2], acc[et*2+1][3],
                        a0, a1, a2, a3, b2, b3);
            }
        }

#pragma unroll
        for (int nt = 0; nt < 8; nt++) {
            int col = nt * 8 + tig * 2;
            int d = wm + gid;
            *(float2*)&dst[d * 64 + col] = make_float2(acc[nt][0], acc[nt][1]);
            *(float2*)&dst[(d + 8) * 64 + col] = make_float2(acc[nt][2], acc[nt][3]);
        }
    }

    // chunk decay means -> mean^128
    __syncthreads();
    if (t < 32) {
        float f = 0.f, s = 0.f;
#pragma unroll
        for (int j = t; j < 128; j += 32) { f += fdm_s[j]; s += sdm_s[j]; }
#pragma unroll
        for (int off = 16; off; off >>= 1) {
            f += __shfl_xor_sync(0xffffffffu, f, off);
            s += __shfl_xor_sync(0xffffffffu, s, off);
        }
        if (t == 0) {
            float gf = f * (1.f / 128.f), gs = s * (1.f / 128.f);
#pragma unroll
            for (int i = 0; i < 7; i++) { gf *= gf; gs *= gs; }
            g_gf[bhn] = gf;
            g_gs[bhn] = gs;
        }
    }
}

// ---------------- K5: decayed prefix scan — batched MLP, float2 -------------
__global__ __launch_bounds__(256) void scan_kernel()
{
    const int bh = blockIdx.x >> 3;
    const int eb = blockIdx.x & 7;
    const int e2 = eb * 256 + threadIdx.x;
    float2* Af2 = (float2*)g_Af;
    float2* As2 = (float2*)g_As;
    const size_t idx2 = (size_t)bh * NCH * 2048 + e2;

    float2 sf = make_float2(0.f, 0.f);
    float2 ss = make_float2(0.f, 0.f);

#pragma unroll 1
    for (int n0 = 0; n0 < NCH; n0 += 8) {
        float2 a[8], b[8];
        float gf[8], gs[8];
#pragma unroll
        for (int j = 0; j < 8; j++) {
            int bhn = bh * NCH + n0 + j;
            gf[j] = g_gf[bhn];
            gs[j] = g_gs[bhn];
            a[j] = Af2[idx2 + (size_t)(n0 + j) * 2048];
            b[j] = As2[idx2 + (size_t)(n0 + j) * 2048];
        }
#pragma unroll
        for (int j = 0; j < 8; j++) {
            sf.x = sf.x * gf[j] + a[j].x;
            sf.y = sf.y * gf[j] + a[j].y;
            ss.x = ss.x * gs[j] + b[j].x;
            ss.y = ss.y * gs[j] + b[j].y;
            a[j] = sf;
            b[j] = ss;
        }
#pragma unroll
        for (int j = 0; j < 8; j++) {
            Af2[idx2 + (size_t)(n0 + j) * 2048] = a[j];
            As2[idx2 + (size_t)(n0 + j) * 2048] = b[j];
        }
    }
}

// ---------------- K6: O = Q@S via fp16 mma, gate/alpha mix -> omix ----------
__global__ __launch_bounds__(256) void outmix_kernel()
{
    __shared__ __half Sfh[64 * ESTR];
    __shared__ __half Ssh[64 * ESTR];
    __shared__ __half Qh[128 * ESTR];
    __shared__ float gA[128], gB[128];

    const int bhn = blockIdx.x;
    const int bh = bhn / NCH, n = bhn % NCH;
    const int b = bh >> 4, h = bh & 15;
    const int t = threadIdx.x;
    const int lane = t & 31;
    const int wid = t >> 5;
    const int gid = lane >> 2;
    const int tig = lane & 3;
    const int posbase = bh * Lq + n * CH;

    // fill Sfh/Ssh (fp32 -> half)
    size_t abase = (size_t)bhn * 4096;
    for (int i = t; i < 1024; i += 256) {
        int d = i >> 4;
        int c4 = (i & 15) * 4;
        float4 f = ((const float4*)(g_Af + abase))[i];
        float4 s = ((const float4*)(g_As + abase))[i];
        __half2 f01 = __floats2half2_rn(f.x, f.y);
        __half2 f23 = __floats2half2_rn(f.z, f.w);
        __half2 s01 = __floats2half2_rn(s.x, s.y);
        __half2 s23 = __floats2half2_rn(s.z, s.w);
        uint2 fo, so;
        fo.x = *(uint32_t*)&f01; fo.y = *(uint32_t*)&f23;
        so.x = *(uint32_t*)&s01; so.y = *(uint32_t*)&s23;
        *(uint2*)&Sfh[d * ESTR + c4] = fo;
        *(uint2*)&Ssh[d * ESTR + c4] = so;
    }
    // fill Qh (copy half)
    {
        const size_t qbase8 = (size_t)posbase * 8;
        for (int i = t; i < 1024; i += 256) {
            int row = i >> 3;
            int c8 = (i & 7) * 8;
            *(uint4*)&Qh[row * ESTR + c8] = ((const uint4*)g_q)[qbase8 + i];
        }
    }
    if (t < 128) {
        int p = posbase + t;
        float psi = g_psi[p];
        float alpha = 0.5f + 0.3f * psi;
        gA[t] = alpha * g_fg[p];
        gB[t] = (1.f - alpha) * g_sg[p];
    }
    __syncthreads();

    // mma: O[l,e] = sum_d Q[l,d] * S[d,e]; warp wid -> l-tile wid*16
    {
        const int lm = wid * 16;
        const uint32_t QU = smem_u32(Qh);
        const uint32_t SfU = smem_u32(Sfh);
        const uint32_t SsU = smem_u32(Ssh);

        const int a_lrow = lane & 15;
        const int a_lcol = (lane >> 4) * 8;
        const int brow_t = (lane & 7) + ((lane >> 3) & 1) * 8;
        const int bcol_t = ((lane >> 4) & 1) * 8;

        float accf[8][4], accs[8][4];
#pragma unroll
        for (int nt = 0; nt < 8; nt++)
#pragma unroll
            for (int c = 0; c < 4; c++) { accf[nt][c] = 0.f; accs[nt][c] = 0.f; }

#pragma unroll
        for (int kc = 0; kc < 4; kc++) {
            int d0 = kc * 16;
            uint32_t a0, a1, a2, a3;
            ldsm_x4(a0, a1, a2, a3,
                QU + (uint32_t)((lm + a_lrow) * ESTR + d0 + a_lcol) * 2u);
#pragma unroll
            for (int et = 0; et < 4; et++) {
                int e0 = et * 16;
                uint32_t b0, b1, b2, b3;
                ldsm_x4_t(b0, b1, b2, b3,
                    SfU + (uint32_t)((d0 + brow_t) * ESTR + e0 + bcol_t) * 2u);
                mma_f16(accf[et*2][0], accf[et*2][1], accf[et*2][2], accf[et*2][3],
                        a0, a1, a2, a3, b0, b1);
                mma_f16(accf[et*2+1][0], accf[et*2+1][1], accf[et*2+1][2], accf[et*2+1][3],
                        a0, a1, a2, a3, b2, b3);
                ldsm_x4_t(b0, b1, b2, b3,
                    SsU + (uint32_t)((d0 + brow_t) * ESTR + e0 + bcol_t) * 2u);
                mma_f16(accs[et*2][0], accs[et*2][1], accs[et*2][2], accs[et*2][3],
                        a0, a1, a2, a3, b0, b1);
                mma_f16(accs[et*2+1][0], accs[et*2+1][1], accs[et*2+1][2], accs[et*2+1][3],
                        a0, a1, a2, a3, b2, b3);
            }
        }

        // epilogue: gated mix, half store
#pragma unroll
        for (int nt = 0; nt < 8; nt++) {
            int col = nt * 8 + tig * 2;
#pragma unroll
            for (int half_ = 0; half_ < 2; half_++) {
                int l = lm + gid + half_ * 8;
                float ga = gA[l], gb = gB[l];
                float v0 = ga * accf[nt][half_ * 2 + 0] + gb * accs[nt][half_ * 2 + 0];
                float v1 = ga * accf[nt][half_ * 2 + 1] + gb * accs[nt][half_ * 2 + 1];
                int lglob = n * CH + l;
                __half2 hv = __floats2half2_rn(v0, v1);
                *(__half2*)(g_omixh + ((size_t)b * Lq + lglob) * 1024 + h * 64 + col) = hv;
            }
        }
    }
}

// ---------------- launch ----------------
extern "C" void kernel_launch(void* const* d_in, const int* in_sizes, int n_in,
                              void* d_out, int out_size)
{
    const float* x   = (const float*)d_in[0];
    const float* Wq  = (const float*)d_in[1];
    const float* Wk  = (const float*)d_in[2];
    const float* Wv  = (const float*)d_in[3];
    const float* Wb  = (const float*)d_in[4];
    const float* Wfd = (const float*)d_in[5];
    const float* fdb = (const float*)d_in[6];
    const float* Wsd = (const float*)d_in[7];
    const float* sdb = (const float*)d_in[8];
    const float* Wfg = (const float*)d_in[9];
    const float* Wsg = (const float*)d_in[10];
    const float* Wo  = (const float*)d_in[11];
    float* out = (float*)d_out;

    void *p_q = nullptr, *p_k = nullptr, *p_v = nullptr;
    void *p_xh = nullptr, *p_wh = nullptr, *p_gwh = nullptr, *p_oh = nullptr;
    cudaGetSymbolAddress(&p_q, g_q);
    cudaGetSymbolAddress(&p_k, g_k);
    cudaGetSymbolAddress(&p_v, g_v);
    cudaGetSymbolAddress(&p_xh, g_xh);
    cudaGetSymbolAddress(&p_wh, g_wh);
    cudaGetSymbolAddress(&p_gwh, g_gwh);
    cudaGetSymbolAddress(&p_oh, g_omixh);

    cudaFuncSetAttribute(gemm_f16_kernel,
                         cudaFuncAttributeMaxDynamicSharedMemorySize, HSMEM);
    cudaFuncSetAttribute(outer_kernel,
                         cudaFuncAttributeMaxDynamicSharedMemorySize, OUTER_SMEM);

    // K0: fused conversions & packing
    prep0_kernel<<<8704, 256>>>(x, Wq, Wk, Wv, Wo, Wb, Wfd, Wsd, Wfg, Wsg);

    // K1+K2: fused QKV + gate projections (1600 blocks), half q/k/v out
    gemm_f16_kernel<<<1600, 256, HSMEM>>>(
        (const __half*)p_xh, (const __half*)p_wh, (const __half*)p_gwh,
        (__half*)p_q, (__half*)p_k, (__half*)p_v, nullptr, fdb, sdb, 0);

    // K4: outer products via fp16 mma (+psi+chunk decay)
    outer_kernel<<<Bq * Hq * NCH, 256, OUTER_SMEM>>>();

    // K5: decayed scan (batched MLP)
    scan_kernel<<<256, 256>>>();

    // K6: Q@S via fp16 mma + gate mixing (half omix)
    outmix_kernel<<<Bq * Hq * NCH, 256>>>();

    // K7: output projection (512 blocks, fp32 out)
    gemm_f16_kernel<<<512, 256, HSMEM>>>(
        (const __half*)p_oh, (const __half*)p_wh + (size_t)3 * Dq * Dq,
        (const __half*)p_gwh, nullptr, nullptr, nullptr, out, fdb, sdb, 1);
}

// round 16
// speedup vs baseline: 1.9400x; 1.0006x over previous
#include <cuda_runtime.h>
#include <cuda_fp16.h>
#include <math.h>
#include <stdint.h>

#define Bq 2
#define Lq 4096
#define Dq 1024
#define Hq 16
#define HDq 64
#define NCH 32
#define CH 128
#define BHL (Bq*Hq*Lq)

// ---- fp16 cp.async GEMM geometry (proven config) ----
#define HSTG 4
#define HBK 32
#define HASTR 40
#define HSTAGE (128*HASTR)
#define HSMEM (HSTG*2*HSTAGE*2)

// ---- recurrence mma tile stride (halves) ----
#define ESTR 72
#define OUTER_SMEM (3*128*ESTR*2)     // Kh, Vh, Vsh = 55296 B

// ---------------- device scratch (no allocations allowed) ----------------
__device__ __half g_xh[Bq*Lq*Dq];
__device__ __half g_wh[4*Dq*Dq];
__device__ __half g_gwh[128*Dq];
__device__ __half g_omixh[Bq*Lq*Dq];
__device__ __half g_q[Bq*Hq*Lq*HDq];
__device__ __half g_k[Bq*Hq*Lq*HDq];
__device__ __half g_v[Bq*Hq*Lq*HDq];
__device__ float g_beta[BHL];
__device__ float g_fd[BHL];
__device__ float g_sd[BHL];
__device__ float g_fg[BHL];
__device__ float g_sg[BHL];
__device__ float g_psi[BHL];
__device__ float g_gf[Bq*Hq*NCH];
__device__ float g_gs[Bq*Hq*NCH];
__device__ __half g_Afh[Bq*Hq*NCH*HDq*HDq];   // half chunk states
__device__ __half g_Ash[Bq*Hq*NCH*HDq*HDq];

__device__ __forceinline__ float sigm(float x) { return 1.f / (1.f + expf(-x)); }

__device__ __forceinline__ uint32_t smem_u32(const void* p) {
    return (uint32_t)__cvta_generic_to_shared(p);
}

__device__ __forceinline__ void cp16h(__half* dst, const __half* src) {
    uint32_t d = (uint32_t)__cvta_generic_to_shared(dst);
    asm volatile("cp.async.cg.shared.global [%0], [%1], 16;" :: "r"(d), "l"(src));
}

__device__ __forceinline__ void ldsm_x4(
    uint32_t& r0, uint32_t& r1, uint32_t& r2, uint32_t& r3, uint32_t addr)
{
    asm volatile("ldmatrix.sync.aligned.m8n8.x4.shared.b16 {%0,%1,%2,%3}, [%4];"
        : "=r"(r0), "=r"(r1), "=r"(r2), "=r"(r3) : "r"(addr));
}

__device__ __forceinline__ void ldsm_x4_t(
    uint32_t& r0, uint32_t& r1, uint32_t& r2, uint32_t& r3, uint32_t addr)
{
    asm volatile("ldmatrix.sync.aligned.m8n8.x4.trans.shared.b16 {%0,%1,%2,%3}, [%4];"
        : "=r"(r0), "=r"(r1), "=r"(r2), "=r"(r3) : "r"(addr));
}

// fp16 k16 mma, f32 accum
__device__ __forceinline__ void mma_f16(
    float& c0, float& c1, float& c2, float& c3,
    uint32_t a0, uint32_t a1, uint32_t a2, uint32_t a3,
    uint32_t b0, uint32_t b1)
{
    asm volatile(
        "mma.sync.aligned.m16n8k16.row.col.f32.f16.f16.f32 "
        "{%0,%1,%2,%3}, {%4,%5,%6,%7}, {%8,%9}, {%0,%1,%2,%3};"
        : "+f"(c0), "+f"(c1), "+f"(c2), "+f"(c3)
        : "r"(a0), "r"(a1), "r"(a2), "r"(a3), "r"(b0), "r"(b1));
}

// ---------------- K0: fused conversions/packing (8704 blocks) ---------------
__global__ __launch_bounds__(256) void prep0_kernel(
    const float* __restrict__ x,
    const float* __restrict__ Wq, const float* __restrict__ Wk,
    const float* __restrict__ Wv, const float* __restrict__ Wo,
    const float* __restrict__ Wbm, const float* __restrict__ Wfd,
    const float* __restrict__ Wsd, const float* __restrict__ Wfg,
    const float* __restrict__ Wsg)
{
    __shared__ __half tile[32][33];
    const int bid = blockIdx.x;
    const int tid = threadIdx.x;

    if (bid < 4096) {
        size_t i = (size_t)bid * 256 + tid;
        const float4* s = (const float4*)x;
        float4 v0 = s[i * 2], v1 = s[i * 2 + 1];
        __half2 h0 = __floats2half2_rn(v0.x, v0.y);
        __half2 h1 = __floats2half2_rn(v0.z, v0.w);
        __half2 h2 = __floats2half2_rn(v1.x, v1.y);
        __half2 h3 = __floats2half2_rn(v1.z, v1.w);
        uint4 o;
        o.x = *(uint32_t*)&h0; o.y = *(uint32_t*)&h1;
        o.z = *(uint32_t*)&h2; o.w = *(uint32_t*)&h3;
        ((uint4*)g_xh)[i] = o;
    } else if (bid < 8192) {
        int idx = bid - 4096;
        int z = idx >> 10;
        int xy = idx & 1023;
        const float* W = (z == 0) ? Wq : (z == 1) ? Wk : (z == 2) ? Wv : Wo;
        __half* WT = g_wh + (size_t)z * Dq * Dq;
        int x0 = (xy & 31) * 32;
        int y0 = (xy >> 5) * 32;
        int tx = tid & 31, ty = tid >> 5;
#pragma unroll
        for (int i = 0; i < 4; i++)
            tile[ty + 8 * i][tx] = __float2half_rn(W[(size_t)(y0 + ty + 8 * i) * 1024 + x0 + tx]);
        __syncthreads();
#pragma unroll
        for (int i = 0; i < 4; i++)
            WT[(size_t)(x0 + ty + 8 * i) * 1024 + y0 + tx] = tile[tx][ty + 8 * i];
    } else {
        int idx = (bid - 8192) * 256 + tid;
        int n = idx >> 10, k = idx & 1023;
        __half val = __float2half_rn(0.f);
        if (n < 80) {
            int which = n >> 4, h = n & 15;
            const float* Wp = (which == 0) ? Wbm : (which == 1) ? Wfd
                             : (which == 2) ? Wsd : (which == 3) ? Wfg : Wsg;
            val = __float2half_rn(Wp[k * 16 + h]);
        }
        g_gwh[n * 1024 + k] = val;
    }
}

// ---------------- K1(+K2)/K7: fp16 cp.async GEMM, ldmatrix fragments --------
__global__ __launch_bounds__(256, 2) void gemm_f16_kernel(
    const __half* __restrict__ A, const __half* __restrict__ WTq,
    const __half* __restrict__ WTg,
    __half* __restrict__ H0, __half* __restrict__ H1, __half* __restrict__ H2,
    float* __restrict__ Cout,
    const float* __restrict__ fdb, const float* __restrict__ sdb,
    int phase)
{
    extern __shared__ __half smh[];
    __half* As = smh;
    __half* Bs = smh + HSTG * HSTAGE;

    const int bid = blockIdx.x;
    int mode, bm, bn, z = 0;
    const __half* WT;
    __half* H = H0;
    if (phase == 0) {
        if (bid < 1536) {
            z = bid >> 9;
            int idx = bid & 511;
            bn = (idx & 7) * 128;
            bm = (idx >> 3) * 128;
            mode = 1;
            WT = WTq + (size_t)z * Dq * Dq;
            H = (z == 0) ? H0 : (z == 1) ? H1 : H2;
        } else {
            bm = (bid - 1536) * 128;
            bn = 0;
            mode = 3;
            WT = WTg;
        }
    } else {
        bn = (bid & 7) * 128;
        bm = (bid >> 3) * 128;
        mode = 0;
        WT = WTq;
    }

    const int tid = threadIdx.x;
    const int lane = tid & 31;
    const int wid = tid >> 5;
    const int gid = lane >> 2;
    const int tig = lane & 3;
    const int warpM = (wid & 1) * 64;
    const int warpN = (wid >> 1) * 32;

    const int l_r = tid >> 2;
    const int l_c = (tid & 3) * 8;

    const int a_lrow = lane & 15;
    const int a_lcol = (lane >> 4) * 8;
    const int b_lrow = ((lane >> 4) & 1) * 8 + (lane & 7);
    const int b_lcol = ((lane >> 3) & 1) * 8;

    float acc[4][4][4];
#pragma unroll
    for (int mt = 0; mt < 4; mt++)
#pragma unroll
        for (int nt = 0; nt < 4; nt++)
#pragma unroll
            for (int c = 0; c < 4; c++) acc[mt][nt][c] = 0.f;

    const __half* Ab0 = A + (size_t)(bm + l_r) * 1024 + l_c;
    const __half* Ab1 = A + (size_t)(bm + l_r + 64) * 1024 + l_c;
    const __half* Bb0 = WT + (size_t)(bn + l_r) * 1024 + l_c;
    const __half* Bb1 = WT + (size_t)(bn + l_r + 64) * 1024 + l_c;
    __half* AsD0 = As + l_r * HASTR + l_c;
    __half* AsD1 = As + (l_r + 64) * HASTR + l_c;
    __half* BsD0 = Bs + l_r * HASTR + l_c;
    __half* BsD1 = Bs + (l_r + 64) * HASTR + l_c;

    const uint32_t AsU = smem_u32(As);
    const uint32_t BsU = smem_u32(Bs);

#pragma unroll
    for (int s = 0; s < HSTG - 1; s++) {
        int k0 = s * HBK;
        cp16h(AsD0 + s * HSTAGE, Ab0 + k0);
        cp16h(AsD1 + s * HSTAGE, Ab1 + k0);
        cp16h(BsD0 + s * HSTAGE, Bb0 + k0);
        cp16h(BsD1 + s * HSTAGE, Bb1 + k0);
        asm volatile("cp.async.commit_group;");
    }

#pragma unroll 1
    for (int t = 0; t < 32; t++) {
        asm volatile("cp.async.wait_group 2;");
        __syncthreads();

        const uint32_t AscU = AsU + (uint32_t)((t & 3) * HSTAGE) * 2u;
        const uint32_t BscU = BsU + (uint32_t)((t & 3) * HSTAGE) * 2u;

        uint32_t af[4][4];
        uint32_t br[2][4];
#pragma unroll
        for (int mt = 0; mt < 4; mt++) {
            uint32_t addr = AscU +
                (uint32_t)((warpM + mt * 16 + a_lrow) * HASTR + a_lcol) * 2u;
            ldsm_x4(af[mt][0], af[mt][1], af[mt][2], af[mt][3], addr);
        }
#pragma unroll
        for (int np = 0; np < 2; np++) {
            uint32_t addr = BscU +
                (uint32_t)((warpN + np * 16 + b_lrow) * HASTR + b_lcol) * 2u;
            ldsm_x4(br[np][0], br[np][1], br[np][2], br[np][3], addr);
        }

        if (t + 3 < 32) {
            int s = (t + 3) & 3;
            int k0 = (t + 3) * HBK;
            cp16h(AsD0 + s * HSTAGE, Ab0 + k0);
            cp16h(AsD1 + s * HSTAGE, Ab1 + k0);
            cp16h(BsD0 + s * HSTAGE, Bb0 + k0);
            cp16h(BsD1 + s * HSTAGE, Bb1 + k0);
        }
        asm volatile("cp.async.commit_group;");

#pragma unroll
        for (int nt = 0; nt < 4; nt++) {
            uint32_t b0 = br[nt >> 1][(nt & 1) * 2 + 0];
            uint32_t b1 = br[nt >> 1][(nt & 1) * 2 + 1];
#pragma unroll
            for (int mt = 0; mt < 4; mt++) {
                mma_f16(acc[mt][nt][0], acc[mt][nt][1], acc[mt][nt][2], acc[mt][nt][3],
                        af[mt][0], af[mt][1], af[mt][2], af[mt][3], b0, b1);
            }
        }

#pragma unroll
        for (int mt = 0; mt < 4; mt++) {
            uint32_t addr = AscU +
                (uint32_t)((warpM + mt * 16 + a_lrow) * HASTR + 16 + a_lcol) * 2u;
            ldsm_x4(af[mt][0], af[mt][1], af[mt][2], af[mt][3], addr);
        }
#pragma unroll
        for (int np = 0; np < 2; np++) {
            uint32_t addr = BscU +
                (uint32_t)((warpN + np * 16 + b_lrow) * HASTR + 16 + b_lcol) * 2u;
            ldsm_x4(br[np][0], br[np][1], br[np][2], br[np][3], addr);
        }
#pragma unroll
        for (int nt = 0; nt < 4; nt++) {
            uint32_t b0 = br[nt >> 1][(nt & 1) * 2 + 0];
            uint32_t b1 = br[nt >> 1][(nt & 1) * 2 + 1];
#pragma unroll
            for (int mt = 0; mt < 4; mt++) {
                mma_f16(acc[mt][nt][0], acc[mt][nt][1], acc[mt][nt][2], acc[mt][nt][3],
                        af[mt][0], af[mt][1], af[mt][2], af[mt][3], b0, b1);
            }
        }
    }

    // epilogue
#pragma unroll
    for (int mt = 0; mt < 4; mt++) {
#pragma unroll
        for (int nt = 0; nt < 4; nt++) {
            int row = bm + warpM + mt * 16 + gid;
            int col = bn + warpN + nt * 8 + tig * 2;
#pragma unroll
            for (int half_ = 0; half_ < 2; half_++) {
                int r = row + half_ * 8;
                float v0 = acc[mt][nt][half_ * 2 + 0];
                float v1 = acc[mt][nt][half_ * 2 + 1];
                int bb = r >> 12, l = r & 4095;
                if (mode == 1) {
                    v0 = v0 * (1.f / (1.f + expf(-v0)));
                    v1 = v1 * (1.f / (1.f + expf(-v1)));
                    int h = col >> 6, hd = col & 63;
                    __half2 hv = __floats2half2_rn(v0, v1);
                    *(__half2*)(H + (((size_t)(bb * Hq + h) * Lq + l) * HDq) + hd) = hv;
                } else if (mode == 3) {
#pragma unroll
                    for (int cc = 0; cc < 2; cc++) {
                        int cl = col + cc;
                        if (cl < 80) {
                            int which = cl >> 4, h = cl & 15;
                            float s = (cc == 0) ? v0 : v1;
                            if (which == 1) s += fdb[h];
                            if (which == 2) s += sdb[h];
                            float val = sigm(s);
                            float* dst = (which == 0) ? g_beta : (which == 1) ? g_fd
                                        : (which == 2) ? g_sd : (which == 3) ? g_fg : g_sg;
                            dst[(bb * Hq + h) * Lq + l] = val;
                        }
                    }
                } else {
                    *(float2*)(Cout + (size_t)r * 1024 + col) = make_float2(v0, v1);
                }
            }
        }
    }
}

// ---------------- K4: outer products via fp16 mma (+psi+chunk decay) --------
__global__ __launch_bounds__(256) void outer_kernel()
{
    extern __shared__ __half osm[];
    __half* Kh  = osm;                       // [128][ESTR]
    __half* Vh  = osm + 128 * ESTR;
    __half* Vsh = osm + 2 * 128 * ESTR;
    __shared__ float S2f[128];
    __shared__ float fdm_s[128];
    __shared__ float sdm_s[128];

    const int bhn = blockIdx.x;
    const int bh = bhn / NCH, n = bhn % NCH;
    const int t = threadIdx.x;
    const int lane = t & 31;
    const int wid = t >> 5;
    const int gid = lane >> 2;
    const int tig = lane & 3;
    const int posbase = bh * Lq + n * CH;
    const size_t kvbase8 = (size_t)posbase * 8;

    for (int i = t; i < 1024; i += 256) {
        int row = i >> 3;
        int c8 = (i & 7) * 8;
        float b = g_beta[posbase + row];
        uint4 kr = ((const uint4*)g_k)[kvbase8 + i];
        uint4 vr = ((const uint4*)g_v)[kvbase8 + i];
        const __half2* kh = (const __half2*)&kr;
        const __half2* vh = (const __half2*)&vr;
        uint4 ko, vo;
        __half2* kop = (__half2*)&ko;
        __half2* vop = (__half2*)&vo;
#pragma unroll
        for (int j = 0; j < 4; j++) {
            float2 kf = __half22float2(kh[j]);
            float2 vf = __half22float2(vh[j]);
            kop[j] = __floats2half2_rn(kf.x * b, kf.y * b);
            vop[j] = __floats2half2_rn(vf.x * b, vf.y * b);
        }
        *(uint4*)&Kh[row * ESTR + c8] = ko;
        *(uint4*)&Vh[row * ESTR + c8] = vo;
    }
    __syncthreads();

    {
        int r = t >> 1, q = t & 1;
        const __half2* kp = (const __half2*)&Kh[r * ESTR + q * 32];
        const __half2* vp = (const __half2*)&Vh[r * ESTR + q * 32];
        float kk = 0.f, vv = 0.f, kv = 0.f;
#pragma unroll
        for (int j = 0; j < 16; j++) {
            float2 a = __half22float2(kp[j]);
            float2 b = __half22float2(vp[j]);
            kk += a.x * a.x + a.y * a.y;
            vv += b.x * b.x + b.y * b.y;
            kv += a.x * b.x + a.y * b.y;
        }
        kk += __shfl_xor_sync(0xffffffffu, kk, 1);
        vv += __shfl_xor_sync(0xffffffffu, vv, 1);
        kv += __shfl_xor_sync(0xffffffffu, kv, 1);
        if (q == 0) {
            float kn = sqrtf(kk) + 1e-8f;
            float vn = sqrtf(vv) + 1e-8f;
            float praw = fabsf(kv) / (kn * vn);
            float psi = sigm(3.f * praw);
            float sur = sigm((psi - 0.5f) * 10.f);
            S2f[r] = sur * sur;
            int p = posbase + r;
            g_psi[p] = psi;
            fdm_s[r] = g_fd[p] * (1.f - 0.1f * psi);
            sdm_s[r] = g_sd[p] * (1.f - 0.05f * psi);
        }
    }
    __syncthreads();

    for (int i = t; i < 1024; i += 256) {
        int row = i >> 3;
        int c8 = (i & 7) * 8;
        float s2 = S2f[row];
        uint4 vr = *(const uint4*)&Vh[row * ESTR + c8];
        const __half2* vh = (const __half2*)&vr;
        uint4 vo;
        __half2* vop = (__half2*)&vo;
#pragma unroll
        for (int j = 0; j < 4; j++) {
            float2 vf = __half22float2(vh[j]);
            vop[j] = __floats2half2_rn(vf.x * s2, vf.y * s2);
        }
        *(uint4*)&Vsh[row * ESTR + c8] = vo;
    }
    __syncthreads();

    {
        const bool slow = (wid >= 4);
        const int wm = (wid & 3) * 16;
        const uint32_t AU = smem_u32(slow ? Vsh : Vh);
        const uint32_t KU = smem_u32(Kh);
        __half* dst = (slow ? g_Ash : g_Afh) + (size_t)bhn * 4096;

        const int arow_t = (lane & 7) + ((lane >> 4) & 1) * 8;
        const int acol_t = ((lane >> 3) & 1) * 8;
        const int brow_t = (lane & 7) + ((lane >> 3) & 1) * 8;
        const int bcol_t = ((lane >> 4) & 1) * 8;

        float acc[8][4];
#pragma unroll
        for (int nt = 0; nt < 8; nt++)
#pragma unroll
            for (int c = 0; c < 4; c++) acc[nt][c] = 0.f;

#pragma unroll
        for (int kc = 0; kc < 8; kc++) {
            int l0 = kc * 16;
            uint32_t a0, a1, a2, a3;
            ldsm_x4_t(a0, a1, a2, a3,
                AU + (uint32_t)((l0 + arow_t) * ESTR + wm + acol_t) * 2u);
#pragma unroll
            for (int et = 0; et < 4; et++) {
                int e0 = et * 16;
                uint32_t b0, b1, b2, b3;
                ldsm_x4_t(b0, b1, b2, b3,
                    KU + (uint32_t)((l0 + brow_t) * ESTR + e0 + bcol_t) * 2u);
                mma_f16(acc[et*2][0], acc[et*2][1], acc[et*2][2], acc[et*2][3],
                        a0, a1, a2, a3, b0, b1);
                mma_f16(acc[et*2+1][0], acc[et*2+1][1], acc[et*2+1][2], acc[et*2+1][3],
                        a0, a1, a2, a3, b2, b3);
            }
        }

#pragma unroll
        for (int nt = 0; nt < 8; nt++) {
            int col = nt * 8 + tig * 2;
            int d = wm + gid;
            *(__half2*)&dst[d * 64 + col] = __floats2half2_rn(acc[nt][0], acc[nt][1]);
            *(__half2*)&dst[(d + 8) * 64 + col] = __floats2half2_rn(acc[nt][2], acc[nt][3]);
        }
    }

    __syncthreads();
    if (t < 32) {
        float f = 0.f, s = 0.f;
#pragma unroll
        for (int j = t; j < 128; j += 32) { f += fdm_s[j]; s += sdm_s[j]; }
#pragma unroll
        for (int off = 16; off; off >>= 1) {
            f += __shfl_xor_sync(0xffffffffu, f, off);
            s += __shfl_xor_sync(0xffffffffu, s, off);
        }
        if (t == 0) {
            float gf = f * (1.f / 128.f), gs = s * (1.f / 128.f);
#pragma unroll
            for (int i = 0; i < 7; i++) { gf *= gf; gs *= gs; }
            g_gf[bhn] = gf;
            g_gs[bhn] = gs;
        }
    }
}

// ---------------- K5: decayed prefix scan — half states, batched MLP --------
// 256 blocks: bh = bid>>3, eb = bid&7; half2 granularity (2048 per chunk).
__global__ __launch_bounds__(256) void scan_kernel()
{
    const int bh = blockIdx.x >> 3;
    const int eb = blockIdx.x & 7;
    const int e2 = eb * 256 + threadIdx.x;       // half2 index 0..2047
    uint32_t* Af2 = (uint32_t*)g_Afh;
    uint32_t* As2 = (uint32_t*)g_Ash;
    const size_t idx2 = (size_t)bh * NCH * 2048 + e2;

    float2 sf = make_float2(0.f, 0.f);
    float2 ss = make_float2(0.f, 0.f);

#pragma unroll 1
    for (int n0 = 0; n0 < NCH; n0 += 8) {
        uint32_t a[8], b[8];
        float gf[8], gs[8];
#pragma unroll
        for (int j = 0; j < 8; j++) {
            int bhn = bh * NCH + n0 + j;
            gf[j] = g_gf[bhn];
            gs[j] = g_gs[bhn];
            a[j] = Af2[idx2 + (size_t)(n0 + j) * 2048];
            b[j] = As2[idx2 + (size_t)(n0 + j) * 2048];
        }
#pragma unroll
        for (int j = 0; j < 8; j++) {
            float2 av = __half22float2(*(__half2*)&a[j]);
            float2 bv = __half22float2(*(__half2*)&b[j]);
            sf.x = sf.x * gf[j] + av.x;
            sf.y = sf.y * gf[j] + av.y;
            ss.x = ss.x * gs[j] + bv.x;
            ss.y = ss.y * gs[j] + bv.y;
            __half2 so = __floats2half2_rn(sf.x, sf.y);
            __half2 to = __floats2half2_rn(ss.x, ss.y);
            a[j] = *(uint32_t*)&so;
            b[j] = *(uint32_t*)&to;
        }
#pragma unroll
        for (int j = 0; j < 8; j++) {
            Af2[idx2 + (size_t)(n0 + j) * 2048] = a[j];
            As2[idx2 + (size_t)(n0 + j) * 2048] = b[j];
        }
    }
}

// ---------------- K6: O = Q@S via fp16 mma, gate/alpha mix -> omix ----------
__global__ __launch_bounds__(256) void outmix_kernel()
{
    __shared__ __half Sfh[64 * ESTR];
    __shared__ __half Ssh[64 * ESTR];
    __shared__ __half Qh[128 * ESTR];
    __shared__ float gA[128], gB[128];

    const int bhn = blockIdx.x;
    const int bh = bhn / NCH, n = bhn % NCH;
    const int b = bh >> 4, h = bh & 15;
    const int t = threadIdx.x;
    const int lane = t & 31;
    const int wid = t >> 5;
    const int gid = lane >> 2;
    const int tig = lane & 3;
    const int posbase = bh * Lq + n * CH;

    // fill Sfh/Ssh: raw half copy (512 uint4)
    {
        const size_t sbase8 = (size_t)bhn * 512;   // uint4 index into g_Afh
        for (int i = t; i < 512; i += 256) {
            int d = i >> 3;
            int c8 = (i & 7) * 8;
            *(uint4*)&Sfh[d * ESTR + c8] = ((const uint4*)g_Afh)[sbase8 + i];
            *(uint4*)&Ssh[d * ESTR + c8] = ((const uint4*)g_Ash)[sbase8 + i];
        }
    }
    // fill Qh (copy half)
    {
        const size_t qbase8 = (size_t)posbase * 8;
        for (int i = t; i < 1024; i += 256) {
            int row = i >> 3;
            int c8 = (i & 7) * 8;
            *(uint4*)&Qh[row * ESTR + c8] = ((const uint4*)g_q)[qbase8 + i];
        }
    }
    if (t < 128) {
        int p = posbase + t;
        float psi = g_psi[p];
        float alpha = 0.5f + 0.3f * psi;
        gA[t] = alpha * g_fg[p];
        gB[t] = (1.f - alpha) * g_sg[p];
    }
    __syncthreads();

    {
        const int lm = wid * 16;
        const uint32_t QU = smem_u32(Qh);
        const uint32_t SfU = smem_u32(Sfh);
        const uint32_t SsU = smem_u32(Ssh);

        const int a_lrow = lane & 15;
        const int a_lcol = (lane >> 4) * 8;
        const int brow_t = (lane & 7) + ((lane >> 3) & 1) * 8;
        const int bcol_t = ((lane >> 4) & 1) * 8;

        float accf[8][4], accs[8][4];
#pragma unroll
        for (int nt = 0; nt < 8; nt++)
#pragma unroll
            for (int c = 0; c < 4; c++) { accf[nt][c] = 0.f; accs[nt][c] = 0.f; }

#pragma unroll
        for (int kc = 0; kc < 4; kc++) {
            int d0 = kc * 16;
            uint32_t a0, a1, a2, a3;
            ldsm_x4(a0, a1, a2, a3,
                QU + (uint32_t)((lm + a_lrow) * ESTR + d0 + a_lcol) * 2u);
#pragma unroll
            for (int et = 0; et < 4; et++) {
                int e0 = et * 16;
                uint32_t b0, b1, b2, b3;
                ldsm_x4_t(b0, b1, b2, b3,
                    SfU + (uint32_t)((d0 + brow_t) * ESTR + e0 + bcol_t) * 2u);
                mma_f16(accf[et*2][0], accf[et*2][1], accf[et*2][2], accf[et*2][3],
                        a0, a1, a2, a3, b0, b1);
                mma_f16(accf[et*2+1][0], accf[et*2+1][1], accf[et*2+1][2], accf[et*2+1][3],
                        a0, a1, a2, a3, b2, b3);
                ldsm_x4_t(b0, b1, b2, b3,
                    SsU + (uint32_t)((d0 + brow_t) * ESTR + e0 + bcol_t) * 2u);
                mma_f16(accs[et*2][0], accs[et*2][1], accs[et*2][2], accs[et*2][3],
                        a0, a1, a2, a3, b0, b1);
                mma_f16(accs[et*2+1][0], accs[et*2+1][1], accs[et*2+1][2], accs[et*2+1][3],
                        a0, a1, a2, a3, b2, b3);
            }
        }

#pragma unroll
        for (int nt = 0; nt < 8; nt++) {
            int col = nt * 8 + tig * 2;
#pragma unroll
            for (int half_ = 0; half_ < 2; half_++) {
                int l = lm + gid + half_ * 8;
                float ga = gA[l], gb = gB[l];
                float v0 = ga * accf[nt][half_ * 2 + 0] + gb * accs[nt][half_ * 2 + 0];
                float v1 = ga * accf[nt][half_ * 2 + 1] + gb * accs[nt][half_ * 2 + 1];
                int lglob = n * CH + l;
                __half2 hv = __floats2half2_rn(v0, v1);
                *(__half2*)(g_omixh + ((size_t)b * Lq + lglob) * 1024 + h * 64 + col) = hv;
            }
        }
    }
}

// ---------------- launch ----------------
extern "C" void kernel_launch(void* const* d_in, const int* in_sizes, int n_in,
                              void* d_out, int out_size)
{
    const float* x   = (const float*)d_in[0];
    const float* Wq  = (const float*)d_in[1];
    const float* Wk  = (const float*)d_in[2];
    const float* Wv  = (const float*)d_in[3];
    const float* Wb  = (const float*)d_in[4];
    const float* Wfd = (const float*)d_in[5];
    const float* fdb = (const float*)d_in[6];
    const float* Wsd = (const float*)d_in[7];
    const float* sdb = (const float*)d_in[8];
    const float* Wfg = (const float*)d_in[9];
    const float* Wsg = (const float*)d_in[10];
    const float* Wo  = (const float*)d_in[11];
    float* out = (float*)d_out;

    void *p_q = nullptr, *p_k = nullptr, *p_v = nullptr;
    void *p_xh = nullptr, *p_wh = nullptr, *p_gwh = nullptr, *p_oh = nullptr;
    cudaGetSymbolAddress(&p_q, g_q);
    cudaGetSymbolAddress(&p_k, g_k);
    cudaGetSymbolAddress(&p_v, g_v);
    cudaGetSymbolAddress(&p_xh, g_xh);
    cudaGetSymbolAddress(&p_wh, g_wh);
    cudaGetSymbolAddress(&p_gwh, g_gwh);
    cudaGetSymbolAddress(&p_oh, g_omixh);

    cudaFuncSetAttribute(gemm_f16_kernel,
                         cudaFuncAttributeMaxDynamicSharedMemorySize, HSMEM);
    cudaFuncSetAttribute(outer_kernel,
                         cudaFuncAttributeMaxDynamicSharedMemorySize, OUTER_SMEM);

    // K0: fused conversions & packing
    prep0_kernel<<<8704, 256>>>(x, Wq, Wk, Wv, Wo, Wb, Wfd, Wsd, Wfg, Wsg);

    // K1+K2: fused QKV + gate projections (1600 blocks), half q/k/v out
    gemm_f16_kernel<<<1600, 256, HSMEM>>>(
        (const __half*)p_xh, (const __half*)p_wh, (const __half*)p_gwh,
        (__half*)p_q, (__half*)p_k, (__half*)p_v, nullptr, fdb, sdb, 0);

    // K4: outer products via fp16 mma (+psi+chunk decay) — half states out
    outer_kernel<<<Bq * Hq * NCH, 256, OUTER_SMEM>>>();

    // K5: decayed scan (half states, batched MLP)
    scan_kernel<<<256, 256>>>();

    // K6: Q@S via fp16 mma + gate mixing (half omix)
    outmix_kernel<<<Bq * Hq * NCH, 256>>>();

    // K7: output projection (512 blocks, fp32 out)
    gemm_f16_kernel<<<512, 256, HSMEM>>>(
        (const __half*)p_oh, (const __half*)p_wh + (size_t)3 * Dq * Dq,
        (const __half*)p_gwh, nullptr, nullptr, nullptr, out, fdb, sdb, 1);
}

// round 17
// speedup vs baseline: 2.0197x; 1.0411x over previous
#include <cuda_runtime.h>
#include <cuda_fp16.h>
#include <math.h>
#include <stdint.h>

#define Bq 2
#define Lq 4096
#define Dq 1024
#define Hq 16
#define HDq 64
#define NCH 32
#define CH 128
#define BHL (Bq*Hq*Lq)

// ---- fp16 cp.async GEMM geometry (proven config) ----
#define HSTG 4
#define HBK 32
#define HASTR 40
#define HSTAGE (128*HASTR)
#define HSMEM (HSTG*2*HSTAGE*2)
#define NPERSIST 296                   // 148 SMs x 2 CTAs

// ---- recurrence mma tile stride (halves) ----
#define ESTR 72
#define OUTER_SMEM (3*128*ESTR*2)

// ---------------- device scratch (no allocations allowed) ----------------
__device__ __half g_xh[Bq*Lq*Dq];
__device__ __half g_wh[4*Dq*Dq];
__device__ __half g_gwh[128*Dq];
__device__ __half g_omixh[Bq*Lq*Dq];
__device__ __half g_q[Bq*Hq*Lq*HDq];
__device__ __half g_k[Bq*Hq*Lq*HDq];
__device__ __half g_v[Bq*Hq*Lq*HDq];
__device__ float g_beta[BHL];
__device__ float g_fd[BHL];
__device__ float g_sd[BHL];
__device__ float g_fg[BHL];
__device__ float g_sg[BHL];
__device__ float g_psi[BHL];
__device__ float g_gf[Bq*Hq*NCH];
__device__ float g_gs[Bq*Hq*NCH];
__device__ __half g_Afh[Bq*Hq*NCH*HDq*HDq];
__device__ __half g_Ash[Bq*Hq*NCH*HDq*HDq];

__device__ __forceinline__ float sigm(float x) { return 1.f / (1.f + expf(-x)); }

__device__ __forceinline__ uint32_t smem_u32(const void* p) {
    return (uint32_t)__cvta_generic_to_shared(p);
}

__device__ __forceinline__ void cp16h(__half* dst, const __half* src) {
    uint32_t d = (uint32_t)__cvta_generic_to_shared(dst);
    asm volatile("cp.async.cg.shared.global [%0], [%1], 16;" :: "r"(d), "l"(src));
}

__device__ __forceinline__ void ldsm_x4(
    uint32_t& r0, uint32_t& r1, uint32_t& r2, uint32_t& r3, uint32_t addr)
{
    asm volatile("ldmatrix.sync.aligned.m8n8.x4.shared.b16 {%0,%1,%2,%3}, [%4];"
        : "=r"(r0), "=r"(r1), "=r"(r2), "=r"(r3) : "r"(addr));
}

__device__ __forceinline__ void ldsm_x4_t(
    uint32_t& r0, uint32_t& r1, uint32_t& r2, uint32_t& r3, uint32_t addr)
{
    asm volatile("ldmatrix.sync.aligned.m8n8.x4.trans.shared.b16 {%0,%1,%2,%3}, [%4];"
        : "=r"(r0), "=r"(r1), "=r"(r2), "=r"(r3) : "r"(addr));
}

// fp16 k16 mma, f32 accum
__device__ __forceinline__ void mma_f16(
    float& c0, float& c1, float& c2, float& c3,
    uint32_t a0, uint32_t a1, uint32_t a2, uint32_t a3,
    uint32_t b0, uint32_t b1)
{
    asm volatile(
        "mma.sync.aligned.m16n8k16.row.col.f32.f16.f16.f32 "
        "{%0,%1,%2,%3}, {%4,%5,%6,%7}, {%8,%9}, {%0,%1,%2,%3};"
        : "+f"(c0), "+f"(c1), "+f"(c2), "+f"(c3)
        : "r"(a0), "r"(a1), "r"(a2), "r"(a3), "r"(b0), "r"(b1));
}

// ---------------- K0: fused conversions/packing (8704 blocks) ---------------
__global__ __launch_bounds__(256) void prep0_kernel(
    const float* __restrict__ x,
    const float* __restrict__ Wq, const float* __restrict__ Wk,
    const float* __restrict__ Wv, const float* __restrict__ Wo,
    const float* __restrict__ Wbm, const float* __restrict__ Wfd,
    const float* __restrict__ Wsd, const float* __restrict__ Wfg,
    const float* __restrict__ Wsg)
{
    __shared__ __half tile[32][33];
    const int bid = blockIdx.x;
    const int tid = threadIdx.x;

    if (bid < 4096) {
        size_t i = (size_t)bid * 256 + tid;
        const float4* s = (const float4*)x;
        float4 v0 = s[i * 2], v1 = s[i * 2 + 1];
        __half2 h0 = __floats2half2_rn(v0.x, v0.y);
        __half2 h1 = __floats2half2_rn(v0.z, v0.w);
        __half2 h2 = __floats2half2_rn(v1.x, v1.y);
        __half2 h3 = __floats2half2_rn(v1.z, v1.w);
        uint4 o;
        o.x = *(uint32_t*)&h0; o.y = *(uint32_t*)&h1;
        o.z = *(uint32_t*)&h2; o.w = *(uint32_t*)&h3;
        ((uint4*)g_xh)[i] = o;
    } else if (bid < 8192) {
        int idx = bid - 4096;
        int z = idx >> 10;
        int xy = idx & 1023;
        const float* W = (z == 0) ? Wq : (z == 1) ? Wk : (z == 2) ? Wv : Wo;
        __half* WT = g_wh + (size_t)z * Dq * Dq;
        int x0 = (xy & 31) * 32;
        int y0 = (xy >> 5) * 32;
        int tx = tid & 31, ty = tid >> 5;
#pragma unroll
        for (int i = 0; i < 4; i++)
            tile[ty + 8 * i][tx] = __float2half_rn(W[(size_t)(y0 + ty + 8 * i) * 1024 + x0 + tx]);
        __syncthreads();
#pragma unroll
        for (int i = 0; i < 4; i++)
            WT[(size_t)(x0 + ty + 8 * i) * 1024 + y0 + tx] = tile[tx][ty + 8 * i];
    } else {
        int idx = (bid - 8192) * 256 + tid;
        int n = idx >> 10, k = idx & 1023;
        __half val = __float2half_rn(0.f);
        if (n < 80) {
            int which = n >> 4, h = n & 15;
            const float* Wp = (which == 0) ? Wbm : (which == 1) ? Wfd
                             : (which == 2) ? Wsd : (which == 3) ? Wfg : Wsg;
            val = __float2half_rn(Wp[k * 16 + h]);
        }
        g_gwh[n * 1024 + k] = val;
    }
}

// ---------------- K1(+K2)/K7: persistent fp16 cp.async GEMM -----------------
// phase 0: 1600 tiles — [0,1536) QKV (silu+head, half out), [1536,1600) gates.
// phase 1: 512 tiles — K7 plain fp32 Cout. Grid = NPERSIST, grid-stride tiles.
__global__ __launch_bounds__(256, 2) void gemm_f16_kernel(
    const __half* __restrict__ A, const __half* __restrict__ WTq,
    const __half* __restrict__ WTg,
    __half* __restrict__ H0, __half* __restrict__ H1, __half* __restrict__ H2,
    float* __restrict__ Cout,
    const float* __restrict__ fdb, const float* __restrict__ sdb,
    int phase)
{
    extern __shared__ __half smh[];
    __half* As = smh;
    __half* Bs = smh + HSTG * HSTAGE;

    const int tid = threadIdx.x;
    const int lane = tid & 31;
    const int wid = tid >> 5;
    const int gid = lane >> 2;
    const int tig = lane & 3;
    const int warpM = (wid & 1) * 64;
    const int warpN = (wid >> 1) * 32;

    const int l_r = tid >> 2;
    const int l_c = (tid & 3) * 8;

    const int a_lrow = lane & 15;
    const int a_lcol = (lane >> 4) * 8;
    const int b_lrow = ((lane >> 4) & 1) * 8 + (lane & 7);
    const int b_lcol = ((lane >> 3) & 1) * 8;

    const uint32_t AsU = smem_u32(As);
    const uint32_t BsU = smem_u32(Bs);

    const int ntiles = (phase == 0) ? 1600 : 512;

#pragma unroll 1
    for (int tileId = blockIdx.x; tileId < ntiles; tileId += NPERSIST) {
        int mode, bm, bn, z = 0;
        const __half* WT;
        __half* H = H0;
        if (phase == 0) {
            if (tileId < 1536) {
                z = tileId >> 9;
                int idx = tileId & 511;
                bn = (idx & 7) * 128;
                bm = (idx >> 3) * 128;
                mode = 1;
                WT = WTq + (size_t)z * Dq * Dq;
                H = (z == 0) ? H0 : (z == 1) ? H1 : H2;
            } else {
                bm = (tileId - 1536) * 128;
                bn = 0;
                mode = 3;
                WT = WTg;
            }
        } else {
            bn = (tileId & 7) * 128;
            bm = (tileId >> 3) * 128;
            mode = 0;
            WT = WTq;
        }

        float acc[4][4][4];
#pragma unroll
        for (int mt = 0; mt < 4; mt++)
#pragma unroll
            for (int nt = 0; nt < 4; nt++)
#pragma unroll
                for (int c = 0; c < 4; c++) acc[mt][nt][c] = 0.f;

        const __half* Ab0 = A + (size_t)(bm + l_r) * 1024 + l_c;
        const __half* Ab1 = A + (size_t)(bm + l_r + 64) * 1024 + l_c;
        const __half* Bb0 = WT + (size_t)(bn + l_r) * 1024 + l_c;
        const __half* Bb1 = WT + (size_t)(bn + l_r + 64) * 1024 + l_c;
        __half* AsD0 = As + l_r * HASTR + l_c;
        __half* AsD1 = As + (l_r + 64) * HASTR + l_c;
        __half* BsD0 = Bs + l_r * HASTR + l_c;
        __half* BsD1 = Bs + (l_r + 64) * HASTR + l_c;

#pragma unroll
        for (int s = 0; s < HSTG - 1; s++) {
            int k0 = s * HBK;
            cp16h(AsD0 + s * HSTAGE, Ab0 + k0);
            cp16h(AsD1 + s * HSTAGE, Ab1 + k0);
            cp16h(BsD0 + s * HSTAGE, Bb0 + k0);
            cp16h(BsD1 + s * HSTAGE, Bb1 + k0);
            asm volatile("cp.async.commit_group;");
        }

#pragma unroll 1
        for (int t = 0; t < 32; t++) {
            asm volatile("cp.async.wait_group 2;");
            __syncthreads();

            const uint32_t AscU = AsU + (uint32_t)((t & 3) * HSTAGE) * 2u;
            const uint32_t BscU = BsU + (uint32_t)((t & 3) * HSTAGE) * 2u;

            uint32_t af[4][4];
            uint32_t br[2][4];
#pragma unroll
            for (int mt = 0; mt < 4; mt++) {
                uint32_t addr = AscU +
                    (uint32_t)((warpM + mt * 16 + a_lrow) * HASTR + a_lcol) * 2u;
                ldsm_x4(af[mt][0], af[mt][1], af[mt][2], af[mt][3], addr);
            }
#pragma unroll
            for (int np = 0; np < 2; np++) {
                uint32_t addr = BscU +
                    (uint32_t)((warpN + np * 16 + b_lrow) * HASTR + b_lcol) * 2u;
                ldsm_x4(br[np][0], br[np][1], br[np][2], br[np][3], addr);
            }

            if (t + 3 < 32) {
                int s = (t + 3) & 3;
                int k0 = (t + 3) * HBK;
                cp16h(AsD0 + s * HSTAGE, Ab0 + k0);
                cp16h(AsD1 + s * HSTAGE, Ab1 + k0);
                cp16h(BsD0 + s * HSTAGE, Bb0 + k0);
                cp16h(BsD1 + s * HSTAGE, Bb1 + k0);
            }
            asm volatile("cp.async.commit_group;");

#pragma unroll
            for (int nt = 0; nt < 4; nt++) {
                uint32_t b0 = br[nt >> 1][(nt & 1) * 2 + 0];
                uint32_t b1 = br[nt >> 1][(nt & 1) * 2 + 1];
#pragma unroll
                for (int mt = 0; mt < 4; mt++) {
                    mma_f16(acc[mt][nt][0], acc[mt][nt][1], acc[mt][nt][2], acc[mt][nt][3],
                            af[mt][0], af[mt][1], af[mt][2], af[mt][3], b0, b1);
                }
            }

#pragma unroll
            for (int mt = 0; mt < 4; mt++) {
                uint32_t addr = AscU +
                    (uint32_t)((warpM + mt * 16 + a_lrow) * HASTR + 16 + a_lcol) * 2u;
                ldsm_x4(af[mt][0], af[mt][1], af[mt][2], af[mt][3], addr);
            }
#pragma unroll
            for (int np = 0; np < 2; np++) {
                uint32_t addr = BscU +
                    (uint32_t)((warpN + np * 16 + b_lrow) * HASTR + 16 + b_lcol) * 2u;
                ldsm_x4(br[np][0], br[np][1], br[np][2], br[np][3], addr);
            }
#pragma unroll
            for (int nt = 0; nt < 4; nt++) {
                uint32_t b0 = br[nt >> 1][(nt & 1) * 2 + 0];
                uint32_t b1 = br[nt >> 1][(nt & 1) * 2 + 1];
#pragma unroll
                for (int mt = 0; mt < 4; mt++) {
                    mma_f16(acc[mt][nt][0], acc[mt][nt][1], acc[mt][nt][2], acc[mt][nt][3],
                            af[mt][0], af[mt][1], af[mt][2], af[mt][3], b0, b1);
                }
            }
        }

        // drain stale (empty) groups before next tile's prologue reuses buffers
        asm volatile("cp.async.wait_group 0;");

        // epilogue
#pragma unroll
        for (int mt = 0; mt < 4; mt++) {
#pragma unroll
            for (int nt = 0; nt < 4; nt++) {
                int row = bm + warpM + mt * 16 + gid;
                int col = bn + warpN + nt * 8 + tig * 2;
#pragma unroll
                for (int half_ = 0; half_ < 2; half_++) {
                    int r = row + half_ * 8;
                    float v0 = acc[mt][nt][half_ * 2 + 0];
                    float v1 = acc[mt][nt][half_ * 2 + 1];
                    int bb = r >> 12, l = r & 4095;
                    if (mode == 1) {
                        v0 = v0 * (1.f / (1.f + expf(-v0)));
                        v1 = v1 * (1.f / (1.f + expf(-v1)));
                        int h = col >> 6, hd = col & 63;
                        __half2 hv = __floats2half2_rn(v0, v1);
                        *(__half2*)(H + (((size_t)(bb * Hq + h) * Lq + l) * HDq) + hd) = hv;
                    } else if (mode == 3) {
#pragma unroll
                        for (int cc = 0; cc < 2; cc++) {
                            int cl = col + cc;
                            if (cl < 80) {
                                int which = cl >> 4, h = cl & 15;
                                float s = (cc == 0) ? v0 : v1;
                                if (which == 1) s += fdb[h];
                                if (which == 2) s += sdb[h];
                                float val = sigm(s);
                                float* dst = (which == 0) ? g_beta : (which == 1) ? g_fd
                                            : (which == 2) ? g_sd : (which == 3) ? g_fg : g_sg;
                                dst[(bb * Hq + h) * Lq + l] = val;
                            }
                        }
                    } else {
                        *(float2*)(Cout + (size_t)r * 1024 + col) = make_float2(v0, v1);
                    }
                }
            }
        }
        __syncthreads();
    }
}

// ---------------- K4: outer products via fp16 mma (+psi+chunk decay) --------
__global__ __launch_bounds__(256) void outer_kernel()
{
    extern __shared__ __half osm[];
    __half* Kh  = osm;
    __half* Vh  = osm + 128 * ESTR;
    __half* Vsh = osm + 2 * 128 * ESTR;
    __shared__ float S2f[128];
    __shared__ float fdm_s[128];
    __shared__ float sdm_s[128];

    const int bhn = blockIdx.x;
    const int bh = bhn / NCH, n = bhn % NCH;
    const int t = threadIdx.x;
    const int lane = t & 31;
    const int wid = t >> 5;
    const int gid = lane >> 2;
    const int tig = lane & 3;
    const int posbase = bh * Lq + n * CH;
    const size_t kvbase8 = (size_t)posbase * 8;

    for (int i = t; i < 1024; i += 256) {
        int row = i >> 3;
        int c8 = (i & 7) * 8;
        float b = g_beta[posbase + row];
        uint4 kr = ((const uint4*)g_k)[kvbase8 + i];
        uint4 vr = ((const uint4*)g_v)[kvbase8 + i];
        const __half2* kh = (const __half2*)&kr;
        const __half2* vh = (const __half2*)&vr;
        uint4 ko, vo;
        __half2* kop = (__half2*)&ko;
        __half2* vop = (__half2*)&vo;
#pragma unroll
        for (int j = 0; j < 4; j++) {
            float2 kf = __half22float2(kh[j]);
            float2 vf = __half22float2(vh[j]);
            kop[j] = __floats2half2_rn(kf.x * b, kf.y * b);
            vop[j] = __floats2half2_rn(vf.x * b, vf.y * b);
        }
        *(uint4*)&Kh[row * ESTR + c8] = ko;
        *(uint4*)&Vh[row * ESTR + c8] = vo;
    }
    __syncthreads();

    {
        int r = t >> 1, q = t & 1;
        const __half2* kp = (const __half2*)&Kh[r * ESTR + q * 32];
        const __half2* vp = (const __half2*)&Vh[r * ESTR + q * 32];
        float kk = 0.f, vv = 0.f, kv = 0.f;
#pragma unroll
        for (int j = 0; j < 16; j++) {
            float2 a = __half22float2(kp[j]);
            float2 b = __half22float2(vp[j]);
            kk += a.x * a.x + a.y * a.y;
            vv += b.x * b.x + b.y * b.y;
            kv += a.x * b.x + a.y * b.y;
        }
        kk += __shfl_xor_sync(0xffffffffu, kk, 1);
        vv += __shfl_xor_sync(0xffffffffu, vv, 1);
        kv += __shfl_xor_sync(0xffffffffu, kv, 1);
        if (q == 0) {
            float kn = sqrtf(kk) + 1e-8f;
            float vn = sqrtf(vv) + 1e-8f;
            float praw = fabsf(kv) / (kn * vn);
            float psi = sigm(3.f * praw);
            float sur = sigm((psi - 0.5f) * 10.f);
            S2f[r] = sur * sur;
            int p = posbase + r;
            g_psi[p] = psi;
            fdm_s[r] = g_fd[p] * (1.f - 0.1f * psi);
            sdm_s[r] = g_sd[p] * (1.f - 0.05f * psi);
        }
    }
    __syncthreads();

    for (int i = t; i < 1024; i += 256) {
        int row = i >> 3;
        int c8 = (i & 7) * 8;
        float s2 = S2f[row];
        uint4 vr = *(const uint4*)&Vh[row * ESTR + c8];
        const __half2* vh = (const __half2*)&vr;
        uint4 vo;
        __half2* vop = (__half2*)&vo;
#pragma unroll
        for (int j = 0; j < 4; j++) {
            float2 vf = __half22float2(vh[j]);
            vop[j] = __floats2half2_rn(vf.x * s2, vf.y * s2);
        }
        *(uint4*)&Vsh[row * ESTR + c8] = vo;
    }
    __syncthreads();

    {
        const bool slow = (wid >= 4);
        const int wm = (wid & 3) * 16;
        const uint32_t AU = smem_u32(slow ? Vsh : Vh);
        const uint32_t KU = smem_u32(Kh);
        __half* dst = (slow ? g_Ash : g_Afh) + (size_t)bhn * 4096;

        const int arow_t = (lane & 7) + ((lane >> 4) & 1) * 8;
        const int acol_t = ((lane >> 3) & 1) * 8;
        const int brow_t = (lane & 7) + ((lane >> 3) & 1) * 8;
        const int bcol_t = ((lane >> 4) & 1) * 8;

        float acc[8][4];
#pragma unroll
        for (int nt = 0; nt < 8; nt++)
#pragma unroll
            for (int c = 0; c < 4; c++) acc[nt][c] = 0.f;

#pragma unroll
        for (int kc = 0; kc < 8; kc++) {
            int l0 = kc * 16;
            uint32_t a0, a1, a2, a3;
            ldsm_x4_t(a0, a1, a2, a3,
                AU + (uint32_t)((l0 + arow_t) * ESTR + wm + acol_t) * 2u);
#pragma unroll
            for (int et = 0; et < 4; et++) {
                int e0 = et * 16;
                uint32_t b0, b1, b2, b3;
                ldsm_x4_t(b0, b1, b2, b3,
                    KU + (uint32_t)((l0 + brow_t) * ESTR + e0 + bcol_t) * 2u);
                mma_f16(acc[et*2][0], acc[et*2][1], acc[et*2][2], acc[et*2][3],
                        a0, a1, a2, a3, b0, b1);
                mma_f16(acc[et*2+1][0], acc[et*2+1][1], acc[et*2+1][2], acc[et*2+1][3],
                        a0, a1, a2, a3, b2, b3);
            }
        }

#pragma unroll
        for (int nt = 0; nt < 8; nt++) {
            int col = nt * 8 + tig * 2;
            int d = wm + gid;
            *(__half2*)&dst[d * 64 + col] = __floats2half2_rn(acc[nt][0], acc[nt][1]);
            *(__half2*)&dst[(d + 8) * 64 + col] = __floats2half2_rn(acc[nt][2], acc[nt][3]);
        }
    }

    __syncthreads();
    if (t < 32) {
        float f = 0.f, s = 0.f;
#pragma unroll
        for (int j = t; j < 128; j += 32) { f += fdm_s[j]; s += sdm_s[j]; }
#pragma unroll
        for (int off = 16; off; off >>= 1) {
            f += __shfl_xor_sync(0xffffffffu, f, off);
            s += __shfl_xor_sync(0xffffffffu, s, off);
        }
        if (t == 0) {
            float gf = f * (1.f / 128.f), gs = s * (1.f / 128.f);
#pragma unroll
            for (int i = 0; i < 7; i++) { gf *= gf; gs *= gs; }
            g_gf[bhn] = gf;
            g_gs[bhn] = gs;
        }
    }
}

// ---------------- K5: decayed prefix scan — half states, 16-chunk batches ---
__global__ __launch_bounds__(256) void scan_kernel()
{
    const int bh = blockIdx.x >> 3;
    const int eb = blockIdx.x & 7;
    const int e2 = eb * 256 + threadIdx.x;       // half2 index 0..2047
    uint32_t* Af2 = (uint32_t*)g_Afh;
    uint32_t* As2 = (uint32_t*)g_Ash;
    const size_t idx2 = (size_t)bh * NCH * 2048 + e2;

    float2 sf = make_float2(0.f, 0.f);
    float2 ss = make_float2(0.f, 0.f);

#pragma unroll
    for (int n0 = 0; n0 < NCH; n0 += 16) {
        uint32_t a[16], b[16];
        float gf[16], gs[16];
#pragma unroll
        for (int j = 0; j < 16; j++) {
            int bhn = bh * NCH + n0 + j;
            gf[j] = g_gf[bhn];
            gs[j] = g_gs[bhn];
            a[j] = Af2[idx2 + (size_t)(n0 + j) * 2048];
            b[j] = As2[idx2 + (size_t)(n0 + j) * 2048];
        }
#pragma unroll
        for (int j = 0; j < 16; j++) {
            float2 av = __half22float2(*(__half2*)&a[j]);
            float2 bv = __half22float2(*(__half2*)&b[j]);
            sf.x = sf.x * gf[j] + av.x;
            sf.y = sf.y * gf[j] + av.y;
            ss.x = ss.x * gs[j] + bv.x;
            ss.y = ss.y * gs[j] + bv.y;
            __half2 so = __floats2half2_rn(sf.x, sf.y);
            __half2 to = __floats2half2_rn(ss.x, ss.y);
            a[j] = *(uint32_t*)&so;
            b[j] = *(uint32_t*)&to;
        }
#pragma unroll
        for (int j = 0; j < 16; j++) {
            Af2[idx2 + (size_t)(n0 + j) * 2048] = a[j];
            As2[idx2 + (size_t)(n0 + j) * 2048] = b[j];
        }
    }
}

// ---------------- K6: O = Q@S via fp16 mma, gate/alpha mix -> omix ----------
__global__ __launch_bounds__(256) void outmix_kernel()
{
    __shared__ __half Sfh[64 * ESTR];
    __shared__ __half Ssh[64 * ESTR];
    __shared__ __half Qh[128 * ESTR];
    __shared__ float gA[128], gB[128];

    const int bhn = blockIdx.x;
    const int bh = bhn / NCH, n = bhn % NCH;
    const int b = bh >> 4, h = bh & 15;
    const int t = threadIdx.x;
    const int lane = t & 31;
    const int wid = t >> 5;
    const int gid = lane >> 2;
    const int tig = lane & 3;
    const int posbase = bh * Lq + n * CH;

    {
        const size_t sbase8 = (size_t)bhn * 512;
        for (int i = t; i < 512; i += 256) {
            int d = i >> 3;
            int c8 = (i & 7) * 8;
            *(uint4*)&Sfh[d * ESTR + c8] = ((const uint4*)g_Afh)[sbase8 + i];
            *(uint4*)&Ssh[d * ESTR + c8] = ((const uint4*)g_Ash)[sbase8 + i];
        }
    }
    {
        const size_t qbase8 = (size_t)posbase * 8;
        for (int i = t; i < 1024; i += 256) {
            int row = i >> 3;
            int c8 = (i & 7) * 8;
            *(uint4*)&Qh[row * ESTR + c8] = ((const uint4*)g_q)[qbase8 + i];
        }
    }
    if (t < 128) {
        int p = posbase + t;
        float psi = g_psi[p];
        float alpha = 0.5f + 0.3f * psi;
        gA[t] = alpha * g_fg[p];
        gB[t] = (1.f - alpha) * g_sg[p];
    }
    __syncthreads();

    {
        const int lm = wid * 16;
        const uint32_t QU = smem_u32(Qh);
        const uint32_t SfU = smem_u32(Sfh);
        const uint32_t SsU = smem_u32(Ssh);

        const int a_lrow = lane & 15;
        const int a_lcol = (lane >> 4) * 8;
        const int brow_t = (lane & 7) + ((lane >> 3) & 1) * 8;
        const int bcol_t = ((lane >> 4) & 1) * 8;

        float accf[8][4], accs[8][4];
#pragma unroll
        for (int nt = 0; nt < 8; nt++)
#pragma unroll
            for (int c = 0; c < 4; c++) { accf[nt][c] = 0.f; accs[nt][c] = 0.f; }

#pragma unroll
        for (int kc = 0; kc < 4; kc++) {
            int d0 = kc * 16;
            uint32_t a0, a1, a2, a3;
            ldsm_x4(a0, a1, a2, a3,
                QU + (uint32_t)((lm + a_lrow) * ESTR + d0 + a_lcol) * 2u);
#pragma unroll
            for (int et = 0; et < 4; et++) {
                int e0 = et * 16;
                uint32_t b0, b1, b2, b3;
                ldsm_x4_t(b0, b1, b2, b3,
                    SfU + (uint32_t)((d0 + brow_t) * ESTR + e0 + bcol_t) * 2u);
                mma_f16(accf[et*2][0], accf[et*2][1], accf[et*2][2], accf[et*2][3],
                        a0, a1, a2, a3, b0, b1);
                mma_f16(accf[et*2+1][0], accf[et*2+1][1], accf[et*2+1][2], accf[et*2+1][3],
                        a0, a1, a2, a3, b2, b3);
                ldsm_x4_t(b0, b1, b2, b3,
                    SsU + (uint32_t)((d0 + brow_t) * ESTR + e0 + bcol_t) * 2u);
                mma_f16(accs[et*2][0], accs[et*2][1], accs[et*2][2], accs[et*2][3],
                        a0, a1, a2, a3, b0, b1);
                mma_f16(accs[et*2+1][0], accs[et*2+1][1], accs[et*2+1][2], accs[et*2+1][3],
                        a0, a1, a2, a3, b2, b3);
            }
        }

#pragma unroll
        for (int nt = 0; nt < 8; nt++) {
            int col = nt * 8 + tig * 2;
#pragma unroll
            for (int half_ = 0; half_ < 2; half_++) {
                int l = lm + gid + half_ * 8;
                float ga = gA[l], gb = gB[l];
                float v0 = ga * accf[nt][half_ * 2 + 0] + gb * accs[nt][half_ * 2 + 0];
                float v1 = ga * accf[nt][half_ * 2 + 1] + gb * accs[nt][half_ * 2 + 1];
                int lglob = n * CH + l;
                __half2 hv = __floats2half2_rn(v0, v1);
                *(__half2*)(g_omixh + ((size_t)b * Lq + lglob) * 1024 + h * 64 + col) = hv;
            }
        }
    }
}

// ---------------- launch ----------------
extern "C" void kernel_launch(void* const* d_in, const int* in_sizes, int n_in,
                              void* d_out, int out_size)
{
    const float* x   = (const float*)d_in[0];
    const float* Wq  = (const float*)d_in[1];
    const float* Wk  = (const float*)d_in[2];
    const float* Wv  = (const float*)d_in[3];
    const float* Wb  = (const float*)d_in[4];
    const float* Wfd = (const float*)d_in[5];
    const float* fdb = (const float*)d_in[6];
    const float* Wsd = (const float*)d_in[7];
    const float* sdb = (const float*)d_in[8];
    const float* Wfg = (const float*)d_in[9];
    const float* Wsg = (const float*)d_in[10];
    const float* Wo  = (const float*)d_in[11];
    float* out = (float*)d_out;

    void *p_q = nullptr, *p_k = nullptr, *p_v = nullptr;
    void *p_xh = nullptr, *p_wh = nullptr, *p_gwh = nullptr, *p_oh = nullptr;
    cudaGetSymbolAddress(&p_q, g_q);
    cudaGetSymbolAddress(&p_k, g_k);
    cudaGetSymbolAddress(&p_v, g_v);
    cudaGetSymbolAddress(&p_xh, g_xh);
    cudaGetSymbolAddress(&p_wh, g_wh);
    cudaGetSymbolAddress(&p_gwh, g_gwh);
    cudaGetSymbolAddress(&p_oh, g_omixh);

    cudaFuncSetAttribute(gemm_f16_kernel,
                         cudaFuncAttributeMaxDynamicSharedMemorySize, HSMEM);
    cudaFuncSetAttribute(outer_kernel,
                         cudaFuncAttributeMaxDynamicSharedMemorySize, OUTER_SMEM);

    // K0: fused conversions & packing
    prep0_kernel<<<8704, 256>>>(x, Wq, Wk, Wv, Wo, Wb, Wfd, Wsd, Wfg, Wsg);

    // K1+K2: persistent fused QKV + gate projections
    gemm_f16_kernel<<<NPERSIST, 256, HSMEM>>>(
        (const __half*)p_xh, (const __half*)p_wh, (const __half*)p_gwh,
        (__half*)p_q, (__half*)p_k, (__half*)p_v, nullptr, fdb, sdb, 0);

    // K4: outer products via fp16 mma (+psi+chunk decay)
    outer_kernel<<<Bq * Hq * NCH, 256, OUTER_SMEM>>>();

    // K5: decayed scan (half states, 16-chunk batches)
    scan_kernel<<<256, 256>>>();

    // K6: Q@S via fp16 mma + gate mixing (half omix)
    outmix_kernel<<<Bq * Hq * NCH, 256>>>();

    // K7: persistent output projection
    gemm_f16_kernel<<<NPERSIST, 256, HSMEM>>>(
        (const __half*)p_oh, (const __half*)p_wh + (size_t)3 * Dq * Dq,
        (const __half*)p_gwh, nullptr, nullptr, nullptr, out, fdb, sdb, 1);
}